// round 12
// baseline (speedup 1.0000x reference)
#include <cuda_runtime.h>

// Problem constants
#define B_    2
#define T_    2048
#define C_    2048
#define NH_   16
#define HS_   128
#define NLQ_  512
#define NLKV_ 512
#define DHR_  64

#define KCAT  576   // 512 + 64 concatenated K for fused S GEMM

// ---------------------------------------------------------------------------
// Static scratch
// ---------------------------------------------------------------------------
__device__ float g_xt  [B_*T_*C_];              // tf32-rounded x
__device__ float g_wdq [NLQ_*C_];
__device__ float g_wdkv[NLKV_*C_];
__device__ float g_wqr [NH_*DHR_*NLQ_];
__device__ float g_wo  [C_*C_];
__device__ float g_wuq [NLQ_*C_];               // rounded W_uq (reshape view [NLQ][C])
__device__ float g_wukT[NLKV_*C_];              // true transpose of W_uk (C,NLKV)->[NLKV][C]
__device__ float g_wuvT[NLKV_*C_];              // true transpose of W_uv (C,NLKV)->[NLKV][C]

__device__ float g_cq   [B_*T_*NLQ_];
__device__ float g_ckv  [B_*T_*KCAT];           // [b,t, 0:512]=c_kv, [512:576]=k_r
__device__ float g_keffT[NH_*NLKV_*NLQ_];       // keffT[h] = k_eff[h]^T
__device__ float g_Rt   [C_*NLKV_];
__device__ float g_qc   [B_*NH_*T_*KCAT];       // [.., 0:512]=q_c, [512:576]=q_r
__device__ float g_cqr  [B_*T_*NH_*DHR_];
__device__ float g_ckr  [B_*T_*DHR_];
__device__ float g_S    [134217728];            // 512 MB [B,NH,T,T]
__device__ float g_VT   [B_*C_*T_];             // 32 MB: VT[b] = Rt @ ckv[b]^T

// ---------------------------------------------------------------------------
__device__ __forceinline__ float ftf32(float x) {
    unsigned u;
    asm("cvt.rna.tf32.f32 %0, %1;" : "=r"(u) : "f"(x));
    return __uint_as_float(u);
}

__device__ __forceinline__ void mma_tf32(float* c, const unsigned* a, const unsigned* b) {
    asm volatile(
        "mma.sync.aligned.m16n8k8.row.col.f32.tf32.tf32.f32 "
        "{%0,%1,%2,%3},{%4,%5,%6,%7},{%8,%9},{%0,%1,%2,%3};\n"
        : "+f"(c[0]), "+f"(c[1]), "+f"(c[2]), "+f"(c[3])
        : "r"(a[0]), "r"(a[1]), "r"(a[2]), "r"(a[3]), "r"(b[0]), "r"(b[1]));
}

__device__ __forceinline__ void cp16(float* dst, const float* src) {
    unsigned d = (unsigned)__cvta_generic_to_shared(dst);
    asm volatile("cp.async.cg.shared.global [%0], [%1], 16;\n" :: "r"(d), "l"(src));
}

// ---------------------------------------------------------------------------
// TF32 tensor-core batched GEMM: C[m,n] = sum_k A[m,k] * B[n,k]  (always B^T)
//   CTA 128x128x32, 3-stage cp.async pipeline (R6-verified ordering),
//   4 warps (2m x 2n), warp tile 64x64 = 4x8 m16n8k8 fragments,
//   128 threads -> 1.0 LDS per MMA (was 1.5 at 32x64 warp tile).
//   causal bit1: skip CTA entirely if col0 > row0 (upper-triangle tile)
//   causal bit0: cap K loop at row0+128 (P columns beyond are zero)
// ---------------------------------------------------------------------------
#define STG_F 9216   // floats per stage (As 4608 + Bs 4608)

__global__ void __launch_bounds__(128, 2) tf32gemm(
    const float* __restrict__ A, const float* __restrict__ B, float* __restrict__ C,
    int K, int lda, int ldb, int ldc, int HB,
    long long sAb, long long sAh,
    long long sBb, long long sBh,
    long long sCb, long long sCh,
    int rnd, int causal)
{
    if ((causal & 2) && (blockIdx.x > blockIdx.y)) return;

    extern __shared__ float sm[];

    const int z  = blockIdx.z;
    const int bb = z / HB, hh = z - bb * HB;
    A += bb * sAb + hh * sAh;
    B += bb * sBb + hh * sBh;
    C += bb * sCb + hh * sCh;

    const int row0 = blockIdx.y * 128;
    const int col0 = blockIdx.x * 128;

    const int tid  = threadIdx.x;
    const int warp = tid >> 5, lane = tid & 31;
    const int wm = warp >> 1, wn = warp & 1;     // 2(m) x 2(n) warps
    const int g  = lane >> 2, t = lane & 3;

    float acc[4][8][4];
    #pragma unroll
    for (int i = 0; i < 4; i++)
        #pragma unroll
        for (int j = 0; j < 8; j++)
            #pragma unroll
            for (int q = 0; q < 4; q++) acc[i][j][q] = 0.f;

    int nk = K >> 5;
    if (causal & 1) {
        int cap = (row0 + 128) >> 5;
        if (cap < nk) nk = cap;
    }

    // As: [m][k] stride 36 ; Bs: [n][k] stride 36
#define ISSUE(KT)                                                                         \
    do {                                                                                  \
        if ((KT) < nk) {                                                                  \
            const int k0_ = (KT) * 32;                                                    \
            float* As_ = sm + ((KT) % 3) * STG_F;                                         \
            float* Bs_ = As_ + 4608;                                                      \
            _Pragma("unroll")                                                             \
            for (int j = 0; j < 8; j++) {                                                 \
                int idx = tid + j * 128;                                                  \
                int row = idx >> 3, q = idx & 7;                                          \
                cp16(As_ + row * 36 + q * 4,                                              \
                     A + (long long)(row0 + row) * lda + k0_ + q * 4);                    \
                cp16(Bs_ + row * 36 + q * 4,                                              \
                     B + (long long)(col0 + row) * ldb + k0_ + q * 4);                    \
            }                                                                             \
        }                                                                                 \
        asm volatile("cp.async.commit_group;\n");                                        \
    } while (0)

    ISSUE(0);
    ISSUE(1);

    for (int kt = 0; kt < nk; kt++) {
        ISSUE(kt + 2);
        asm volatile("cp.async.wait_group 2;\n" ::: "memory");
        __syncthreads();

        const float* As = sm + (kt % 3) * STG_F;
        const float* Bs = As + 4608;

        #pragma unroll
        for (int kk = 0; kk < 32; kk += 8) {
            unsigned af[4][4], bf[8][2];
            #pragma unroll
            for (int i = 0; i < 4; i++) {
                int r = wm * 64 + i * 16 + g;
                af[i][0] = __float_as_uint(As[r * 36 + kk + t]);
                af[i][1] = __float_as_uint(As[(r + 8) * 36 + kk + t]);
                af[i][2] = __float_as_uint(As[r * 36 + kk + t + 4]);
                af[i][3] = __float_as_uint(As[(r + 8) * 36 + kk + t + 4]);
            }
            #pragma unroll
            for (int j = 0; j < 8; j++) {
                int c = wn * 64 + j * 8 + g;
                bf[j][0] = __float_as_uint(Bs[c * 36 + kk + t]);
                bf[j][1] = __float_as_uint(Bs[c * 36 + kk + t + 4]);
            }
            #pragma unroll
            for (int i = 0; i < 4; i++)
                #pragma unroll
                for (int j = 0; j < 8; j++)
                    mma_tf32(acc[i][j], af[i], bf[j]);
        }
        __syncthreads();
    }
#undef ISSUE

    // Epilogue
    #pragma unroll
    for (int i = 0; i < 4; i++) {
        long long r0 = row0 + wm * 64 + i * 16 + g;
        #pragma unroll
        for (int j = 0; j < 8; j++) {
            int cc = col0 + wn * 64 + j * 8 + 2 * t;
            float v0 = acc[i][j][0], v1 = acc[i][j][1];
            float v2 = acc[i][j][2], v3 = acc[i][j][3];
            if (rnd) { v0 = ftf32(v0); v1 = ftf32(v1); v2 = ftf32(v2); v3 = ftf32(v3); }
            *(float2*)(C + r0 * ldc + cc)       = make_float2(v0, v1);
            *(float2*)(C + (r0 + 8) * ldc + cc) = make_float2(v2, v3);
        }
    }
}

// ---------------------------------------------------------------------------
// Elementwise round-to-tf32
// ---------------------------------------------------------------------------
__global__ void round_tf32_kernel(const float* __restrict__ in, float* __restrict__ out, int n4)
{
    int i = blockIdx.x * 256 + threadIdx.x;
    if (i >= n4) return;
    float4 v = ((const float4*)in)[i];
    v.x = ftf32(v.x); v.y = ftf32(v.y); v.z = ftf32(v.z); v.w = ftf32(v.w);
    ((float4*)out)[i] = v;
}

// ---------------------------------------------------------------------------
// Transpose + round: in [R][Cc] -> out [Cc][R], tf32-rounded. R,Cc % 32 == 0.
// ---------------------------------------------------------------------------
__global__ void transpose_round_kernel(const float* __restrict__ in, float* __restrict__ out,
                                       int R, int Cc)
{
    __shared__ float tile[32][33];
    int c0 = blockIdx.x * 32, r0 = blockIdx.y * 32;
    int tx = threadIdx.x, ty = threadIdx.y;
    #pragma unroll
    for (int i = 0; i < 32; i += 8)
        tile[ty + i][tx] = in[(long long)(r0 + ty + i) * Cc + c0 + tx];
    __syncthreads();
    #pragma unroll
    for (int i = 0; i < 32; i += 8)
        out[(long long)(c0 + ty + i) * R + r0 + tx] = ftf32(tile[tx][ty + i]);
}

// ---------------------------------------------------------------------------
// SIMT SGEMM fallback (only the tiny c_kr projection, full fp32)
// ---------------------------------------------------------------------------
__global__ void sgemm64(const float* __restrict__ A, const float* __restrict__ B,
                        float* __restrict__ C,
                        int M, int N, int K, int lda, int ldb, int ldc)
{
    const int row0 = blockIdx.y * 64;
    const int col0 = blockIdx.x * 64;

    __shared__ float As[16][68];
    __shared__ float Bs[16][68];

    const int tid = threadIdx.x;
    const int tx  = tid & 15;
    const int ty  = tid >> 4;
    const int ar = tid >> 2;
    const int ak = (tid & 3) * 4;

    float acc[4][4] = {};

    for (int k0 = 0; k0 < K; k0 += 16) {
        float4 av = *(const float4*)(A + (long long)(row0 + ar) * lda + (k0 + ak));
        As[ak + 0][ar] = av.x;
        As[ak + 1][ar] = av.y;
        As[ak + 2][ar] = av.z;
        As[ak + 3][ar] = av.w;
        float4 bv = *(const float4*)(B + (long long)(col0 + ar) * ldb + (k0 + ak)); // B^T
        Bs[ak + 0][ar] = bv.x;
        Bs[ak + 1][ar] = bv.y;
        Bs[ak + 2][ar] = bv.z;
        Bs[ak + 3][ar] = bv.w;
        __syncthreads();

        #pragma unroll
        for (int kk = 0; kk < 16; kk++) {
            float4 a4 = *(const float4*)&As[kk][ty * 4];
            float4 b4 = *(const float4*)&Bs[kk][tx * 4];
            float aa[4] = {a4.x, a4.y, a4.z, a4.w};
            float bbv[4] = {b4.x, b4.y, b4.z, b4.w};
            #pragma unroll
            for (int i = 0; i < 4; i++)
                #pragma unroll
                for (int j = 0; j < 4; j++)
                    acc[i][j] += aa[i] * bbv[j];
        }
        __syncthreads();
    }

    #pragma unroll
    for (int i = 0; i < 4; i++)
        #pragma unroll
        for (int j = 0; j < 4; j++)
            C[(long long)(row0 + ty * 4 + i) * ldc + (col0 + tx * 4 + j)] = acc[i][j];
}

// ---------------------------------------------------------------------------
// RoPE kernels (outputs tf32-rounded, written into concatenated buffers)
// ---------------------------------------------------------------------------
__global__ void rope_q_kernel(const float* __restrict__ in, float* __restrict__ qcbuf,
                              const float* __restrict__ cosp, const float* __restrict__ sinp)
{
    int j = blockIdx.x * blockDim.x + threadIdx.x;
    if (j >= B_ * T_ * NH_ * (DHR_ / 2)) return;
    int i = j & 31;
    int h = (j >> 5) & 15;
    int t = (j >> 9) & 2047;
    int b = j >> 20;
    float c = cosp[t * 32 + i];
    float s = sinp[t * 32 + i];
    float re = in[2 * j], im = in[2 * j + 1];
    long long base = ((long long)(b * NH_ + h) * T_ + t) * KCAT + 512 + 2 * i;
    qcbuf[base]     = ftf32(re * c - im * s);
    qcbuf[base + 1] = ftf32(re * s + im * c);
}

__global__ void rope_k_kernel(const float* __restrict__ in, float* __restrict__ ckvbuf,
                              const float* __restrict__ cosp, const float* __restrict__ sinp)
{
    int j = blockIdx.x * blockDim.x + threadIdx.x;
    if (j >= B_ * T_ * (DHR_ / 2)) return;
    int i = j & 31;
    int t = (j >> 5) & 2047;
    int b = j >> 16;
    float c = cosp[t * 32 + i];
    float s = sinp[t * 32 + i];
    float re = in[2 * j], im = in[2 * j + 1];
    long long base = ((long long)b * T_ + t) * KCAT + 512 + 2 * i;
    ckvbuf[base]     = ftf32(re * c - im * s);
    ckvbuf[base + 1] = ftf32(re * s + im * c);
}

// ---------------------------------------------------------------------------
// Causal softmax, in-place, tf32-rounded output. One block per row.
// Writes cols [0, ceil128(t+1)) — exactly what the capped y GEMM reads.
// ---------------------------------------------------------------------------
__global__ void softmax_causal_kernel(float* __restrict__ S)
{
    const float scale = 0.07216878364870323f;   // 1/sqrt(192)
    long long row = blockIdx.x;
    int t = (int)(row % T_);
    int limit = ((t >> 7) + 1) << 7;            // multiple of 128 covering t
    float* p = S + row * (long long)T_;
    int tid = threadIdx.x;

    float v[8];
    float m = -3.0e38f;
    #pragma unroll
    for (int j = 0; j < 8; j++) {
        int i = tid + j * 256;
        float x = -3.0e38f;
        if (i <= t) x = p[i] * scale;
        v[j] = x;
        m = fmaxf(m, x);
    }

    __shared__ float red[256];
    red[tid] = m;
    __syncthreads();
    for (int s = 128; s > 0; s >>= 1) {
        if (tid < s) red[tid] = fmaxf(red[tid], red[tid + s]);
        __syncthreads();
    }
    m = red[0];
    __syncthreads();

    float sum = 0.f;
    #pragma unroll
    for (int j = 0; j < 8; j++) {
        int i = tid + j * 256;
        float e = (i <= t) ? __expf(v[j] - m) : 0.f;
        v[j] = e;
        sum += e;
    }
    red[tid] = sum;
    __syncthreads();
    for (int s = 128; s > 0; s >>= 1) {
        if (tid < s) red[tid] += red[tid + s];
        __syncthreads();
    }
    float inv = 1.0f / red[0];

    #pragma unroll
    for (int j = 0; j < 8; j++) {
        int i = tid + j * 256;
        if (i < limit) p[i] = ftf32(v[j] * inv);
    }
}

// ---------------------------------------------------------------------------
// Host
// ---------------------------------------------------------------------------
#define SMEM_BYTES (3 * STG_F * 4)   // 110592

static inline void launch_tf32(const float* A, const float* B, float* C,
                               int M, int N, int K, int lda, int ldb, int ldc,
                               int batches, int HB,
                               long long sAb, long long sAh,
                               long long sBb, long long sBh,
                               long long sCb, long long sCh,
                               int rnd, int causal)
{
    dim3 grid(N / 128, M / 128, batches);
    tf32gemm<<<grid, 128, SMEM_BYTES>>>(A, B, C, K, lda, ldb, ldc, HB,
                                        sAb, sAh, sBb, sBh, sCb, sCh, rnd, causal);
}

static inline void round_tf32(const float* in, float* out, long long n)
{
    int n4 = (int)(n / 4);
    round_tf32_kernel<<<(n4 + 255) / 256, 256>>>(in, out, n4);
}

static inline void transpose_round(const float* in, float* out, int R, int Cc)
{
    dim3 grid(Cc / 32, R / 32);
    transpose_round_kernel<<<grid, dim3(32, 8)>>>(in, out, R, Cc);
}

extern "C" void kernel_launch(void* const* d_in, const int* in_sizes, int n_in,
                              void* d_out, int out_size)
{
    (void)in_sizes; (void)n_in; (void)out_size;
    const float* x     = (const float*)d_in[0];
    const float* cosp  = (const float*)d_in[1];
    const float* sinp  = (const float*)d_in[2];
    const float* W_dq  = (const float*)d_in[3];
    const float* W_uq  = (const float*)d_in[4];
    const float* W_dkv = (const float*)d_in[5];
    const float* W_uk  = (const float*)d_in[6];
    const float* W_uv  = (const float*)d_in[7];
    const float* W_qr  = (const float*)d_in[8];
    const float* W_kr  = (const float*)d_in[9];
    const float* W_o   = (const float*)d_in[10];
    float* y = (float*)d_out;

    static int smem_set = 0;
    if (!smem_set) {
        cudaFuncSetAttribute(tf32gemm, cudaFuncAttributeMaxDynamicSharedMemorySize, SMEM_BYTES);
        smem_set = 1;
    }

    float *xt, *wdq, *wdkv, *wqr, *wo, *wuq, *wukT, *wuvT;
    float *cq, *ckv, *keffT, *Rt, *qc, *cqr, *ckr, *S, *VT;
    cudaGetSymbolAddress((void**)&xt,    g_xt);
    cudaGetSymbolAddress((void**)&wdq,   g_wdq);
    cudaGetSymbolAddress((void**)&wdkv,  g_wdkv);
    cudaGetSymbolAddress((void**)&wqr,   g_wqr);
    cudaGetSymbolAddress((void**)&wo,    g_wo);
    cudaGetSymbolAddress((void**)&wuq,   g_wuq);
    cudaGetSymbolAddress((void**)&wukT,  g_wukT);
    cudaGetSymbolAddress((void**)&wuvT,  g_wuvT);
    cudaGetSymbolAddress((void**)&cq,    g_cq);
    cudaGetSymbolAddress((void**)&ckv,   g_ckv);
    cudaGetSymbolAddress((void**)&keffT, g_keffT);
    cudaGetSymbolAddress((void**)&Rt,    g_Rt);
    cudaGetSymbolAddress((void**)&qc,    g_qc);
    cudaGetSymbolAddress((void**)&cqr,   g_cqr);
    cudaGetSymbolAddress((void**)&ckr,   g_ckr);
    cudaGetSymbolAddress((void**)&S,     g_S);
    cudaGetSymbolAddress((void**)&VT,    g_VT);

    const long long TT   = (long long)T_ * T_;
    const long long T512 = (long long)T_ * 512;
    const long long TKC  = (long long)T_ * KCAT;
    const long long TC   = (long long)T_ * C_;

    // 0) tf32-round raw inputs (5 launches), then the 6th launch is a GEMM so
    //    the ncu -s 5 -c 1 window captures tf32gemm for the next analysis round.
    round_tf32(x,     xt,   (long long)B_*T_*C_);
    round_tf32(W_dq,  wdq,  (long long)NLQ_*C_);
    round_tf32(W_dkv, wdkv, (long long)NLKV_*C_);
    round_tf32(W_qr,  wqr,  (long long)NH_*DHR_*NLQ_);
    round_tf32(W_o,   wo,   (long long)C_*C_);

    // 1) c_q = xt @ wdq^T   [4096,512] (rounded) — 6th launch, profiled
    launch_tf32(xt, wdq, cq, B_*T_, NLQ_, C_, C_, C_, NLQ_,
                1, 1, 0,0, 0,0, 0,0, 1, 0);

    // W_uq: plain round (its reshape view [NLQ][C] is used directly);
    // W_uk / W_uv: true matrix transpose (2048,512) -> [512][2048], rounded.
    round_tf32(W_uq, wuq, (long long)C_*NLQ_);
    transpose_round(W_uk, wukT, C_, NLKV_);
    transpose_round(W_uv, wuvT, C_, NLKV_);

    // 2) c_kv = xt @ wdkv^T -> ckv buffer (ldc=576, rounded)
    launch_tf32(xt, wdkv, ckv, B_*T_, NLKV_, C_, C_, C_, KCAT,
                1, 1, 0,0, 0,0, 0,0, 1, 0);
    // 3) keffT[h][k][q] = sum_d wukT[k][h*128+d] * wuq[q][h*128+d]
    //    (16 batched, 512x512x128; A=wukT lda C_, B=wuq ldb C_, both offset h*HS)
    launch_tf32(wukT, wuq, keffT, NLKV_, NLQ_, HS_, C_, C_, NLQ_,
                NH_, NH_, 0, HS_, 0, HS_, 0, (long long)NLKV_*NLQ_, 1, 0);
    // 4) Rt = wo @ wuvT^T   [2048,512] (rounded): Rt[c][k] = sum_j wo[c][j]*W_uv[j][k]
    launch_tf32(wo, wuvT, Rt, C_, NLKV_, C_, C_, C_, NLKV_,
                1, 1, 0,0, 0,0, 0,0, 1, 0);
    // 5) q_c[b,h] = cq[b] @ keffT[h]^T -> qc buffer (ldc=576, rounded)
    launch_tf32(cq, keffT, qc, T_, NLKV_, NLQ_, NLQ_, NLQ_, KCAT,
                B_*NH_, NH_, T512, 0, 0, (long long)NLKV_*NLQ_,
                (long long)NH_*TKC, TKC, 1, 0);
    // 6) c_qr = cq @ wqr^T  [4096,1024] (rope rounds later)
    launch_tf32(cq, wqr, cqr, B_*T_, NH_*DHR_, NLQ_, NLQ_, NLQ_, NH_*DHR_,
                1, 1, 0,0, 0,0, 0,0, 0, 0);
    // 7) q_r = rope(c_qr) -> qc buffer cols [512:576]
    {
        int n = B_ * T_ * NH_ * (DHR_ / 2);
        rope_q_kernel<<<(n + 255) / 256, 256>>>(cqr, qc, cosp, sinp);
    }
    // 8) c_kr = x @ W_kr^T  [4096,64] (SIMT, full fp32)
    {
        dim3 grid(DHR_ / 64, (B_*T_) / 64, 1);
        sgemm64<<<grid, 256>>>(x, W_kr, ckr, B_*T_, DHR_, C_, C_, C_, DHR_);
    }
    // 9) k_r = rope(c_kr) -> ckv buffer cols [512:576]
    {
        int n = B_ * T_ * (DHR_ / 2);
        rope_k_kernel<<<(n + 255) / 256, 256>>>(ckr, ckv, cosp, sinp);
    }
    // 10) S = [q_c|q_r] @ [c_kv|k_r]^T  (32 batched, 2048x2048x576, causal-skip)
    launch_tf32(qc, ckv, S, T_, T_, KCAT, KCAT, KCAT, T_,
                B_*NH_, NH_, (long long)NH_*TKC, TKC, TKC, 0,
                (long long)NH_*TT, TT, 0, 2);
    // 11) VT[b][c][t] = sum_k Rt[c][k] * ckv[b][t][k]  (2 batched, 2048x2048x512)
    launch_tf32(Rt, ckv, VT, C_, T_, NLKV_, NLKV_, KCAT, T_,
                B_, 1, 0, 0, TKC, 0, TC, 0, 1, 0);
    // 12) causal softmax in place (rounded, trimmed to ceil128(t+1) cols)
    softmax_causal_kernel<<<B_*NH_*T_, 256>>>(S);
    // 13) y[b][t][h*128+c] = sum_s P[b,h][t][s] * VT[b][h*128+c][s]
    //     (32 batched, 2048x128x2048, K capped at row0+128)
    launch_tf32(S, VT, y, T_, HS_, T_, T_, T_, C_,
                B_*NH_, NH_, (long long)NH_*TT, TT, TC, (long long)HS_*T_,
                TC, HS_, 0, 1);
}

// round 13
// speedup vs baseline: 1.3580x; 1.3580x over previous
#include <cuda_runtime.h>
#include <cuda_fp16.h>

// Problem constants
#define B_    2
#define T_    2048
#define C_    2048
#define NH_   16
#define HS_   128
#define NLQ_  512
#define NLKV_ 512
#define DHR_  64

#define KCAT  576   // 512 + 64 concatenated K for fused S GEMM

// ---------------------------------------------------------------------------
// Static scratch (half operands for all tensor GEMMs; fp32 where needed)
// ---------------------------------------------------------------------------
__device__ __align__(256) __half g_xh  [B_*T_*C_];
__device__ __align__(256) __half g_wdq [NLQ_*C_];
__device__ __align__(256) __half g_wdkv[NLKV_*C_];
__device__ __align__(256) __half g_wqr [NH_*DHR_*NLQ_];
__device__ __align__(256) __half g_wo  [C_*C_];
__device__ __align__(256) __half g_wuq [NLQ_*C_];      // reshape view of W_uq
__device__ __align__(256) __half g_wukT[NLKV_*C_];     // transpose of W_uk
__device__ __align__(256) __half g_wuvT[NLKV_*C_];     // transpose of W_uv

__device__ __align__(256) __half g_cq   [B_*T_*NLQ_];
__device__ __align__(256) __half g_ckv  [B_*T_*KCAT];  // [0:512]=c_kv, [512:576]=k_r
__device__ __align__(256) __half g_keffT[NH_*NLKV_*NLQ_];
__device__ __align__(256) __half g_Rt   [C_*NLKV_];
__device__ __align__(256) __half g_qc   [B_*NH_*T_*KCAT]; // [0:512]=q_c, [512:576]=q_r
__device__ __align__(256) __half g_VT   [B_*C_*T_];    // VT[b] = Rt @ ckv[b]^T
__device__ __align__(256) __half g_P    [134217728];   // 256 MB softmax probs (half)

__device__ float g_cqr [B_*T_*NH_*DHR_];
__device__ float g_ckr [B_*T_*DHR_];
__device__ float g_S   [134217728];                    // 512 MB scores (fp32)

// ---------------------------------------------------------------------------
__device__ __forceinline__ void mma_f16(float* c, const unsigned* a, const unsigned* b) {
    asm volatile(
        "mma.sync.aligned.m16n8k16.row.col.f32.f16.f16.f32 "
        "{%0,%1,%2,%3},{%4,%5,%6,%7},{%8,%9},{%0,%1,%2,%3};\n"
        : "+f"(c[0]), "+f"(c[1]), "+f"(c[2]), "+f"(c[3])
        : "r"(a[0]), "r"(a[1]), "r"(a[2]), "r"(a[3]), "r"(b[0]), "r"(b[1]));
}

__device__ __forceinline__ void cp16(void* dst, const __half* src) {
    unsigned d = (unsigned)__cvta_generic_to_shared(dst);
    asm volatile("cp.async.cg.shared.global [%0], [%1], 16;\n" :: "r"(d), "l"(src));
}

// ---------------------------------------------------------------------------
// FP16 tensor-core batched GEMM: C[m,n] = sum_k A[m,k] * B[n,k]  (always B^T)
//   A,B half; C float (outh=0) or half (outh=1); fp32 accumulation.
//   CTA 128x128x32, 3-stage cp.async pipeline (R6-verified ordering),
//   8 warps (4m x 2n), warp tile 32x64 = 2x8 m16n8k16 fragments.
//   causal bit1: skip CTA entirely if col0 > row0 (upper-triangle tile)
//   causal bit0: cap K loop at row0+128 (P columns beyond are zero)
// ---------------------------------------------------------------------------
#define STG_H 10240   // halfs per stage (As 128*40 + Bs 128*40)
#define SMEM_BYTES (3 * STG_H * 2)   // 61440

__global__ void __launch_bounds__(256, 2) hgemm(
    const __half* __restrict__ A, const __half* __restrict__ B, void* __restrict__ Cv,
    int K, int lda, int ldb, int ldc, int HB,
    long long sAb, long long sAh,
    long long sBb, long long sBh,
    long long sCb, long long sCh,
    int outh, int causal)
{
    if ((causal & 2) && (blockIdx.x > blockIdx.y)) return;

    extern __shared__ __half smh[];

    const int z  = blockIdx.z;
    const int bb = z / HB, hh = z - bb * HB;
    A += bb * sAb + hh * sAh;
    B += bb * sBb + hh * sBh;
    const long long coff = bb * sCb + hh * sCh;

    const int row0 = blockIdx.y * 128;
    const int col0 = blockIdx.x * 128;

    const int tid  = threadIdx.x;
    const int warp = tid >> 5, lane = tid & 31;
    const int wm = warp >> 1, wn = warp & 1;     // 4(m) x 2(n)
    const int g  = lane >> 2, t = lane & 3;

    float acc[2][8][4];
    #pragma unroll
    for (int i = 0; i < 2; i++)
        #pragma unroll
        for (int j = 0; j < 8; j++)
            #pragma unroll
            for (int q = 0; q < 4; q++) acc[i][j][q] = 0.f;

    int nk = K >> 5;
    if (causal & 1) {
        int cap = (row0 + 128) >> 5;
        if (cap < nk) nk = cap;
    }

    // As/Bs: [row 0..127][k 0..31] halfs, row stride 40 (16B-aligned, LDS conflict-free)
#define ISSUE(KT)                                                                         \
    do {                                                                                  \
        if ((KT) < nk) {                                                                  \
            const int k0_ = (KT) * 32;                                                    \
            __half* As_ = smh + ((KT) % 3) * STG_H;                                       \
            __half* Bs_ = As_ + 5120;                                                     \
            _Pragma("unroll")                                                             \
            for (int j = 0; j < 2; j++) {                                                 \
                int idx = tid + j * 256;                                                  \
                int row = idx >> 2, q = idx & 3;                                          \
                cp16(As_ + row * 40 + q * 8,                                              \
                     A + (long long)(row0 + row) * lda + k0_ + q * 8);                    \
                cp16(Bs_ + row * 40 + q * 8,                                              \
                     B + (long long)(col0 + row) * ldb + k0_ + q * 8);                    \
            }                                                                             \
        }                                                                                 \
        asm volatile("cp.async.commit_group;\n");                                        \
    } while (0)

    ISSUE(0);
    ISSUE(1);

    for (int kt = 0; kt < nk; kt++) {
        ISSUE(kt + 2);
        asm volatile("cp.async.wait_group 2;\n" ::: "memory");
        __syncthreads();

        const __half* As = smh + (kt % 3) * STG_H;
        const __half* Bs = As + 5120;

        #pragma unroll
        for (int kk = 0; kk < 32; kk += 16) {
            unsigned af[2][4], bf[8][2];
            #pragma unroll
            for (int i = 0; i < 2; i++) {
                int r = wm * 32 + i * 16 + g;
                af[i][0] = *(const unsigned*)&As[r * 40 + kk + 2 * t];
                af[i][1] = *(const unsigned*)&As[(r + 8) * 40 + kk + 2 * t];
                af[i][2] = *(const unsigned*)&As[r * 40 + kk + 8 + 2 * t];
                af[i][3] = *(const unsigned*)&As[(r + 8) * 40 + kk + 8 + 2 * t];
            }
            #pragma unroll
            for (int j = 0; j < 8; j++) {
                int c = wn * 64 + j * 8 + g;
                bf[j][0] = *(const unsigned*)&Bs[c * 40 + kk + 2 * t];
                bf[j][1] = *(const unsigned*)&Bs[c * 40 + kk + 8 + 2 * t];
            }
            #pragma unroll
            for (int i = 0; i < 2; i++)
                #pragma unroll
                for (int j = 0; j < 8; j++)
                    mma_f16(acc[i][j], af[i], bf[j]);
        }
        __syncthreads();
    }
#undef ISSUE

    // Epilogue
    if (outh) {
        __half* Ch = (__half*)Cv + coff;
        #pragma unroll
        for (int i = 0; i < 2; i++) {
            long long r0 = row0 + wm * 32 + i * 16 + g;
            #pragma unroll
            for (int j = 0; j < 8; j++) {
                int cc = col0 + wn * 64 + j * 8 + 2 * t;
                *(__half2*)(Ch + r0 * ldc + cc) =
                    __floats2half2_rn(acc[i][j][0], acc[i][j][1]);
                *(__half2*)(Ch + (r0 + 8) * ldc + cc) =
                    __floats2half2_rn(acc[i][j][2], acc[i][j][3]);
            }
        }
    } else {
        float* Cf = (float*)Cv + coff;
        #pragma unroll
        for (int i = 0; i < 2; i++) {
            long long r0 = row0 + wm * 32 + i * 16 + g;
            #pragma unroll
            for (int j = 0; j < 8; j++) {
                int cc = col0 + wn * 64 + j * 8 + 2 * t;
                *(float2*)(Cf + r0 * ldc + cc) =
                    make_float2(acc[i][j][0], acc[i][j][1]);
                *(float2*)(Cf + (r0 + 8) * ldc + cc) =
                    make_float2(acc[i][j][2], acc[i][j][3]);
            }
        }
    }
}

// ---------------------------------------------------------------------------
// float -> half conversion (n % 8 == 0)
// ---------------------------------------------------------------------------
__global__ void f2h_kernel(const float* __restrict__ in, __half* __restrict__ out, int n8)
{
    int i = blockIdx.x * 256 + threadIdx.x;
    if (i >= n8) return;
    const float4* in4 = (const float4*)in;
    float4 a = in4[2 * i], b = in4[2 * i + 1];
    __half2* o = (__half2*)(out + 8LL * i);
    o[0] = __floats2half2_rn(a.x, a.y);
    o[1] = __floats2half2_rn(a.z, a.w);
    o[2] = __floats2half2_rn(b.x, b.y);
    o[3] = __floats2half2_rn(b.z, b.w);
}

// Transpose float [R][Cc] -> half [Cc][R]. R,Cc % 32 == 0.
__global__ void transpose_h_kernel(const float* __restrict__ in, __half* __restrict__ out,
                                   int R, int Cc)
{
    __shared__ float tile[32][33];
    int c0 = blockIdx.x * 32, r0 = blockIdx.y * 32;
    int tx = threadIdx.x, ty = threadIdx.y;
    #pragma unroll
    for (int i = 0; i < 32; i += 8)
        tile[ty + i][tx] = in[(long long)(r0 + ty + i) * Cc + c0 + tx];
    __syncthreads();
    #pragma unroll
    for (int i = 0; i < 32; i += 8)
        out[(long long)(c0 + ty + i) * R + r0 + tx] = __float2half(tile[tx][ty + i]);
}

// ---------------------------------------------------------------------------
// SIMT SGEMM (tiny c_kr projection, full fp32)
// ---------------------------------------------------------------------------
__global__ void sgemm64(const float* __restrict__ A, const float* __restrict__ B,
                        float* __restrict__ C,
                        int M, int N, int K, int lda, int ldb, int ldc)
{
    const int row0 = blockIdx.y * 64;
    const int col0 = blockIdx.x * 64;

    __shared__ float As[16][68];
    __shared__ float Bs[16][68];

    const int tid = threadIdx.x;
    const int tx  = tid & 15;
    const int ty  = tid >> 4;
    const int ar = tid >> 2;
    const int ak = (tid & 3) * 4;

    float acc[4][4] = {};

    for (int k0 = 0; k0 < K; k0 += 16) {
        float4 av = *(const float4*)(A + (long long)(row0 + ar) * lda + (k0 + ak));
        As[ak + 0][ar] = av.x;
        As[ak + 1][ar] = av.y;
        As[ak + 2][ar] = av.z;
        As[ak + 3][ar] = av.w;
        float4 bv = *(const float4*)(B + (long long)(col0 + ar) * ldb + (k0 + ak)); // B^T
        Bs[ak + 0][ar] = bv.x;
        Bs[ak + 1][ar] = bv.y;
        Bs[ak + 2][ar] = bv.z;
        Bs[ak + 3][ar] = bv.w;
        __syncthreads();

        #pragma unroll
        for (int kk = 0; kk < 16; kk++) {
            float4 a4 = *(const float4*)&As[kk][ty * 4];
            float4 b4 = *(const float4*)&Bs[kk][tx * 4];
            float aa[4] = {a4.x, a4.y, a4.z, a4.w};
            float bbv[4] = {b4.x, b4.y, b4.z, b4.w};
            #pragma unroll
            for (int i = 0; i < 4; i++)
                #pragma unroll
                for (int j = 0; j < 4; j++)
                    acc[i][j] += aa[i] * bbv[j];
        }
        __syncthreads();
    }

    #pragma unroll
    for (int i = 0; i < 4; i++)
        #pragma unroll
        for (int j = 0; j < 4; j++)
            C[(long long)(row0 + ty * 4 + i) * ldc + (col0 + tx * 4 + j)] = acc[i][j];
}

// ---------------------------------------------------------------------------
// RoPE kernels: float in -> half out into concatenated buffers
// ---------------------------------------------------------------------------
__global__ void rope_q_kernel(const float* __restrict__ in, __half* __restrict__ qcbuf,
                              const float* __restrict__ cosp, const float* __restrict__ sinp)
{
    int j = blockIdx.x * blockDim.x + threadIdx.x;
    if (j >= B_ * T_ * NH_ * (DHR_ / 2)) return;
    int i = j & 31;
    int h = (j >> 5) & 15;
    int t = (j >> 9) & 2047;
    int b = j >> 20;
    float c = cosp[t * 32 + i];
    float s = sinp[t * 32 + i];
    float re = in[2 * j], im = in[2 * j + 1];
    long long base = ((long long)(b * NH_ + h) * T_ + t) * KCAT + 512 + 2 * i;
    *(__half2*)(qcbuf + base) = __floats2half2_rn(re * c - im * s, re * s + im * c);
}

__global__ void rope_k_kernel(const float* __restrict__ in, __half* __restrict__ ckvbuf,
                              const float* __restrict__ cosp, const float* __restrict__ sinp)
{
    int j = blockIdx.x * blockDim.x + threadIdx.x;
    if (j >= B_ * T_ * (DHR_ / 2)) return;
    int i = j & 31;
    int t = (j >> 5) & 2047;
    int b = j >> 16;
    float c = cosp[t * 32 + i];
    float s = sinp[t * 32 + i];
    float re = in[2 * j], im = in[2 * j + 1];
    long long base = ((long long)b * T_ + t) * KCAT + 512 + 2 * i;
    *(__half2*)(ckvbuf + base) = __floats2half2_rn(re * c - im * s, re * s + im * c);
}

// ---------------------------------------------------------------------------
// Causal softmax: S (fp32) -> P (fp16). One block per row.
// Writes P cols [0, ceil128(t+1)) — exactly what the capped y GEMM reads.
// ---------------------------------------------------------------------------
__global__ void softmax_causal_kernel(const float* __restrict__ S, __half* __restrict__ P)
{
    const float scale = 0.07216878364870323f;   // 1/sqrt(192)
    long long row = blockIdx.x;
    int t = (int)(row % T_);
    int limit = ((t >> 7) + 1) << 7;            // multiple of 128 covering t
    const float* p = S + row * (long long)T_;
    __half* po = P + row * (long long)T_;
    int tid = threadIdx.x;

    float v[8];
    float m = -3.0e38f;
    #pragma unroll
    for (int j = 0; j < 8; j++) {
        int i = tid + j * 256;
        float x = -3.0e38f;
        if (i <= t) x = p[i] * scale;
        v[j] = x;
        m = fmaxf(m, x);
    }

    __shared__ float red[256];
    red[tid] = m;
    __syncthreads();
    for (int s = 128; s > 0; s >>= 1) {
        if (tid < s) red[tid] = fmaxf(red[tid], red[tid + s]);
        __syncthreads();
    }
    m = red[0];
    __syncthreads();

    float sum = 0.f;
    #pragma unroll
    for (int j = 0; j < 8; j++) {
        int i = tid + j * 256;
        float e = (i <= t) ? __expf(v[j] - m) : 0.f;
        v[j] = e;
        sum += e;
    }
    red[tid] = sum;
    __syncthreads();
    for (int s = 128; s > 0; s >>= 1) {
        if (tid < s) red[tid] += red[tid + s];
        __syncthreads();
    }
    float inv = 1.0f / red[0];

    #pragma unroll
    for (int j = 0; j < 8; j++) {
        int i = tid + j * 256;
        if (i < limit) po[i] = __float2half(v[j] * inv);
    }
}

// ---------------------------------------------------------------------------
// Host
// ---------------------------------------------------------------------------
static inline void launch_h(const __half* A, const __half* B, void* C,
                            int M, int N, int K, int lda, int ldb, int ldc,
                            int batches, int HB,
                            long long sAb, long long sAh,
                            long long sBb, long long sBh,
                            long long sCb, long long sCh,
                            int outh, int causal)
{
    dim3 grid(N / 128, M / 128, batches);
    hgemm<<<grid, 256, SMEM_BYTES>>>(A, B, C, K, lda, ldb, ldc, HB,
                                     sAb, sAh, sBb, sBh, sCb, sCh, outh, causal);
}

static inline void f2h(const float* in, __half* out, long long n)
{
    int n8 = (int)(n / 8);
    f2h_kernel<<<(n8 + 255) / 256, 256>>>(in, out, n8);
}

static inline void transpose_h(const float* in, __half* out, int R, int Cc)
{
    dim3 grid(Cc / 32, R / 32);
    transpose_h_kernel<<<grid, dim3(32, 8)>>>(in, out, R, Cc);
}

extern "C" void kernel_launch(void* const* d_in, const int* in_sizes, int n_in,
                              void* d_out, int out_size)
{
    (void)in_sizes; (void)n_in; (void)out_size;
    const float* x     = (const float*)d_in[0];
    const float* cosp  = (const float*)d_in[1];
    const float* sinp  = (const float*)d_in[2];
    const float* W_dq  = (const float*)d_in[3];
    const float* W_uq  = (const float*)d_in[4];
    const float* W_dkv = (const float*)d_in[5];
    const float* W_uk  = (const float*)d_in[6];
    const float* W_uv  = (const float*)d_in[7];
    const float* W_qr  = (const float*)d_in[8];
    const float* W_kr  = (const float*)d_in[9];
    const float* W_o   = (const float*)d_in[10];
    float* y = (float*)d_out;

    static int smem_set = 0;
    if (!smem_set) {
        cudaFuncSetAttribute(hgemm, cudaFuncAttributeMaxDynamicSharedMemorySize, SMEM_BYTES);
        smem_set = 1;
    }

    __half *xh, *wdq, *wdkv, *wqr, *wo, *wuq, *wukT, *wuvT;
    __half *cq, *ckv, *keffT, *Rt, *qc, *VT, *P;
    float *cqr, *ckr, *S;
    cudaGetSymbolAddress((void**)&xh,    g_xh);
    cudaGetSymbolAddress((void**)&wdq,   g_wdq);
    cudaGetSymbolAddress((void**)&wdkv,  g_wdkv);
    cudaGetSymbolAddress((void**)&wqr,   g_wqr);
    cudaGetSymbolAddress((void**)&wo,    g_wo);
    cudaGetSymbolAddress((void**)&wuq,   g_wuq);
    cudaGetSymbolAddress((void**)&wukT,  g_wukT);
    cudaGetSymbolAddress((void**)&wuvT,  g_wuvT);
    cudaGetSymbolAddress((void**)&cq,    g_cq);
    cudaGetSymbolAddress((void**)&ckv,   g_ckv);
    cudaGetSymbolAddress((void**)&keffT, g_keffT);
    cudaGetSymbolAddress((void**)&Rt,    g_Rt);
    cudaGetSymbolAddress((void**)&qc,    g_qc);
    cudaGetSymbolAddress((void**)&VT,    g_VT);
    cudaGetSymbolAddress((void**)&P,     g_P);
    cudaGetSymbolAddress((void**)&cqr,   g_cqr);
    cudaGetSymbolAddress((void**)&ckr,   g_ckr);
    cudaGetSymbolAddress((void**)&S,     g_S);

    const long long TT   = (long long)T_ * T_;
    const long long T512 = (long long)T_ * 512;
    const long long TKC  = (long long)T_ * KCAT;
    const long long TC   = (long long)T_ * C_;

    // 0) fp16 conversions (5 launches), then the 6th launch is a GEMM so the
    //    ncu -s 5 -c 1 window captures hgemm for the next analysis round.
    f2h(x,     xh,   (long long)B_*T_*C_);
    f2h(W_dq,  wdq,  (long long)NLQ_*C_);
    f2h(W_dkv, wdkv, (long long)NLKV_*C_);
    f2h(W_qr,  wqr,  (long long)NH_*DHR_*NLQ_);
    f2h(W_o,   wo,   (long long)C_*C_);

    // 1) c_q = xh @ wdq^T   [4096,512] (half out) — 6th launch, profiled
    launch_h(xh, wdq, cq, B_*T_, NLQ_, C_, C_, C_, NLQ_,
             1, 1, 0,0, 0,0, 0,0, 1, 0);

    // W_uq: plain convert (reshape view [NLQ][C] used with lda C_);
    // W_uk / W_uv: true transpose (2048,512) -> [512][2048], half.
    f2h(W_uq, wuq, (long long)C_*NLQ_);
    transpose_h(W_uk, wukT, C_, NLKV_);
    transpose_h(W_uv, wuvT, C_, NLKV_);

    // 2) c_kv = xh @ wdkv^T -> ckv buffer (half, ldc=576)
    launch_h(xh, wdkv, ckv, B_*T_, NLKV_, C_, C_, C_, KCAT,
             1, 1, 0,0, 0,0, 0,0, 1, 0);
    // 3) keffT[h][k][q] = sum_d wukT[k][h*128+d] * wuq[q][h*128+d]  (16 batched)
    launch_h(wukT, wuq, keffT, NLKV_, NLQ_, HS_, C_, C_, NLQ_,
             NH_, NH_, 0, HS_, 0, HS_, 0, (long long)NLKV_*NLQ_, 1, 0);
    // 4) Rt = wo @ wuvT^T   [2048,512] (half)
    launch_h(wo, wuvT, Rt, C_, NLKV_, C_, C_, C_, NLKV_,
             1, 1, 0,0, 0,0, 0,0, 1, 0);
    // 5) q_c[b,h] = cq[b] @ keffT[h]^T -> qc buffer (half, ldc=576)
    launch_h(cq, keffT, qc, T_, NLKV_, NLQ_, NLQ_, NLQ_, KCAT,
             B_*NH_, NH_, T512, 0, 0, (long long)NLKV_*NLQ_,
             (long long)NH_*TKC, TKC, 1, 0);
    // 6) c_qr = cq @ wqr^T  [4096,1024] (float out; rope converts)
    launch_h(cq, wqr, cqr, B_*T_, NH_*DHR_, NLQ_, NLQ_, NLQ_, NH_*DHR_,
             1, 1, 0,0, 0,0, 0,0, 0, 0);
    // 7) q_r = rope(c_qr) -> qc buffer cols [512:576] (half)
    {
        int n = B_ * T_ * NH_ * (DHR_ / 2);
        rope_q_kernel<<<(n + 255) / 256, 256>>>(cqr, qc, cosp, sinp);
    }
    // 8) c_kr = x @ W_kr^T  [4096,64] (SIMT, full fp32)
    {
        dim3 grid(DHR_ / 64, (B_*T_) / 64, 1);
        sgemm64<<<grid, 256>>>(x, W_kr, ckr, B_*T_, DHR_, C_, C_, C_, DHR_);
    }
    // 9) k_r = rope(c_kr) -> ckv buffer cols [512:576] (half)
    {
        int n = B_ * T_ * (DHR_ / 2);
        rope_k_kernel<<<(n + 255) / 256, 256>>>(ckr, ckv, cosp, sinp);
    }
    // 10) S = [q_c|q_r] @ [c_kv|k_r]^T  (32 batched, 2048x2048x576, causal-skip, fp32 out)
    launch_h(qc, ckv, S, T_, T_, KCAT, KCAT, KCAT, T_,
             B_*NH_, NH_, (long long)NH_*TKC, TKC, TKC, 0,
             (long long)NH_*TT, TT, 0, 2);
    // 11) VT[b][c][t] = sum_k Rt[c][k] * ckv[b][t][k]  (2 batched, half out)
    launch_h(Rt, ckv, VT, C_, T_, NLKV_, NLKV_, KCAT, T_,
             B_, 1, 0, 0, TKC, 0, TC, 0, 1, 0);
    // 12) causal softmax: S(fp32) -> P(half), cols [0, ceil128(t+1))
    softmax_causal_kernel<<<B_*NH_*T_, 256>>>(S, P);
    // 13) y[b][t][h*128+c] = sum_s P[b,h][t][s] * VT[b][h*128+c][s]
    //     (32 batched, 2048x128x2048, K capped at row0+128, fp32 out)
    launch_h(P, VT, y, T_, HS_, T_, T_, T_, C_,
             B_*NH_, NH_, (long long)NH_*TT, TT, TC, (long long)HS_*T_,
             TC, HS_, 0, 1);
}

// round 14
// speedup vs baseline: 1.4929x; 1.0993x over previous
#include <cuda_runtime.h>
#include <cuda_fp16.h>

// Problem constants
#define B_    2
#define T_    2048
#define C_    2048
#define NH_   16
#define HS_   128
#define NLQ_  512
#define NLKV_ 512
#define DHR_  64

#define KCAT  576   // 512 + 64 concatenated K for fused S GEMM

// ---------------------------------------------------------------------------
// Static scratch (half operands for all tensor GEMMs; fp32 where needed)
// ---------------------------------------------------------------------------
__device__ __align__(256) __half g_xh  [B_*T_*C_];
__device__ __align__(256) __half g_wdq [NLQ_*C_];
__device__ __align__(256) __half g_wdkv[NLKV_*C_];
__device__ __align__(256) __half g_wqr [NH_*DHR_*NLQ_];
__device__ __align__(256) __half g_wo  [C_*C_];
__device__ __align__(256) __half g_wuq [NLQ_*C_];      // reshape view of W_uq
__device__ __align__(256) __half g_wukT[NLKV_*C_];     // transpose of W_uk
__device__ __align__(256) __half g_wuvT[NLKV_*C_];     // transpose of W_uv
__device__ __align__(256) __half g_wkrp[128*C_];       // W_kr padded 64->128 rows (pad stays 0)

__device__ __align__(256) __half g_cq   [B_*T_*NLQ_];
__device__ __align__(256) __half g_ckv  [B_*T_*KCAT];  // [0:512]=c_kv, [512:576]=k_r
__device__ __align__(256) __half g_keffT[NH_*NLKV_*NLQ_];
__device__ __align__(256) __half g_Rt   [C_*NLKV_];
__device__ __align__(256) __half g_qc   [B_*NH_*T_*KCAT]; // [0:512]=q_c, [512:576]=q_r
__device__ __align__(256) __half g_VT   [B_*C_*T_];    // VT[b] = Rt @ ckv[b]^T
__device__ __align__(256) __half g_S    [134217728];   // 256 MB scores->probs (half, in-place)
__device__ __align__(256) __half g_ckrp [B_*T_*128];   // c_kr padded (cols 64:128 garbage-free zero-weight)

__device__ float g_cqr [B_*T_*NH_*DHR_];

// ---------------------------------------------------------------------------
__device__ __forceinline__ void mma_f16(float* c, const unsigned* a, const unsigned* b) {
    asm volatile(
        "mma.sync.aligned.m16n8k16.row.col.f32.f16.f16.f32 "
        "{%0,%1,%2,%3},{%4,%5,%6,%7},{%8,%9},{%0,%1,%2,%3};\n"
        : "+f"(c[0]), "+f"(c[1]), "+f"(c[2]), "+f"(c[3])
        : "r"(a[0]), "r"(a[1]), "r"(a[2]), "r"(a[3]), "r"(b[0]), "r"(b[1]));
}

__device__ __forceinline__ void cp16(void* dst, const __half* src) {
    unsigned d = (unsigned)__cvta_generic_to_shared(dst);
    asm volatile("cp.async.cg.shared.global [%0], [%1], 16;\n" :: "r"(d), "l"(src));
}

// ---------------------------------------------------------------------------
// FP16 tensor-core batched GEMM: C[m,n] = sum_k A[m,k] * B[n,k]  (always B^T)
//   A,B half; C float (outh=0) or half (outh=1); fp32 accumulation.
//   CTA 128x128x32, 3-stage cp.async pipeline (R6-verified ordering),
//   8 warps (4m x 2n), warp tile 32x64 = 2x8 m16n8k16 fragments.
//   causal bit1: skip CTA entirely if col0 > row0 (upper-triangle tile)
//   causal bit0: cap K loop at row0+128 (P columns beyond are zero)
// ---------------------------------------------------------------------------
#define STG_H 10240   // halfs per stage (As 128*40 + Bs 128*40)
#define SMEM_BYTES (3 * STG_H * 2)   // 61440

__global__ void __launch_bounds__(256, 2) hgemm(
    const __half* __restrict__ A, const __half* __restrict__ B, void* __restrict__ Cv,
    int K, int lda, int ldb, int ldc, int HB,
    long long sAb, long long sAh,
    long long sBb, long long sBh,
    long long sCb, long long sCh,
    int outh, int causal)
{
    if ((causal & 2) && (blockIdx.x > blockIdx.y)) return;

    extern __shared__ __half smh[];

    const int z  = blockIdx.z;
    const int bb = z / HB, hh = z - bb * HB;
    A += bb * sAb + hh * sAh;
    B += bb * sBb + hh * sBh;
    const long long coff = bb * sCb + hh * sCh;

    const int row0 = blockIdx.y * 128;
    const int col0 = blockIdx.x * 128;

    const int tid  = threadIdx.x;
    const int warp = tid >> 5, lane = tid & 31;
    const int wm = warp >> 1, wn = warp & 1;     // 4(m) x 2(n)
    const int g  = lane >> 2, t = lane & 3;

    float acc[2][8][4];
    #pragma unroll
    for (int i = 0; i < 2; i++)
        #pragma unroll
        for (int j = 0; j < 8; j++)
            #pragma unroll
            for (int q = 0; q < 4; q++) acc[i][j][q] = 0.f;

    int nk = K >> 5;
    if (causal & 1) {
        int cap = (row0 + 128) >> 5;
        if (cap < nk) nk = cap;
    }

    // As/Bs: [row 0..127][k 0..31] halfs, row stride 40 (16B-aligned, LDS conflict-free)
#define ISSUE(KT)                                                                         \
    do {                                                                                  \
        if ((KT) < nk) {                                                                  \
            const int k0_ = (KT) * 32;                                                    \
            __half* As_ = smh + ((KT) % 3) * STG_H;                                       \
            __half* Bs_ = As_ + 5120;                                                     \
            _Pragma("unroll")                                                             \
            for (int j = 0; j < 2; j++) {                                                 \
                int idx = tid + j * 256;                                                  \
                int row = idx >> 2, q = idx & 3;                                          \
                cp16(As_ + row * 40 + q * 8,                                              \
                     A + (long long)(row0 + row) * lda + k0_ + q * 8);                    \
                cp16(Bs_ + row * 40 + q * 8,                                              \
                     B + (long long)(col0 + row) * ldb + k0_ + q * 8);                    \
            }                                                                             \
        }                                                                                 \
        asm volatile("cp.async.commit_group;\n");                                        \
    } while (0)

    ISSUE(0);
    ISSUE(1);

    for (int kt = 0; kt < nk; kt++) {
        ISSUE(kt + 2);
        asm volatile("cp.async.wait_group 2;\n" ::: "memory");
        __syncthreads();

        const __half* As = smh + (kt % 3) * STG_H;
        const __half* Bs = As + 5120;

        #pragma unroll
        for (int kk = 0; kk < 32; kk += 16) {
            unsigned af[2][4], bf[8][2];
            #pragma unroll
            for (int i = 0; i < 2; i++) {
                int r = wm * 32 + i * 16 + g;
                af[i][0] = *(const unsigned*)&As[r * 40 + kk + 2 * t];
                af[i][1] = *(const unsigned*)&As[(r + 8) * 40 + kk + 2 * t];
                af[i][2] = *(const unsigned*)&As[r * 40 + kk + 8 + 2 * t];
                af[i][3] = *(const unsigned*)&As[(r + 8) * 40 + kk + 8 + 2 * t];
            }
            #pragma unroll
            for (int j = 0; j < 8; j++) {
                int c = wn * 64 + j * 8 + g;
                bf[j][0] = *(const unsigned*)&Bs[c * 40 + kk + 2 * t];
                bf[j][1] = *(const unsigned*)&Bs[c * 40 + kk + 8 + 2 * t];
            }
            #pragma unroll
            for (int i = 0; i < 2; i++)
                #pragma unroll
                for (int j = 0; j < 8; j++)
                    mma_f16(acc[i][j], af[i], bf[j]);
        }
        __syncthreads();
    }
#undef ISSUE

    // Epilogue
    if (outh) {
        __half* Ch = (__half*)Cv + coff;
        #pragma unroll
        for (int i = 0; i < 2; i++) {
            long long r0 = row0 + wm * 32 + i * 16 + g;
            #pragma unroll
            for (int j = 0; j < 8; j++) {
                int cc = col0 + wn * 64 + j * 8 + 2 * t;
                *(__half2*)(Ch + r0 * ldc + cc) =
                    __floats2half2_rn(acc[i][j][0], acc[i][j][1]);
                *(__half2*)(Ch + (r0 + 8) * ldc + cc) =
                    __floats2half2_rn(acc[i][j][2], acc[i][j][3]);
            }
        }
    } else {
        float* Cf = (float*)Cv + coff;
        #pragma unroll
        for (int i = 0; i < 2; i++) {
            long long r0 = row0 + wm * 32 + i * 16 + g;
            #pragma unroll
            for (int j = 0; j < 8; j++) {
                int cc = col0 + wn * 64 + j * 8 + 2 * t;
                *(float2*)(Cf + r0 * ldc + cc) =
                    make_float2(acc[i][j][0], acc[i][j][1]);
                *(float2*)(Cf + (r0 + 8) * ldc + cc) =
                    make_float2(acc[i][j][2], acc[i][j][3]);
            }
        }
    }
}

// ---------------------------------------------------------------------------
// float -> half conversion (n % 8 == 0)
// ---------------------------------------------------------------------------
__global__ void f2h_kernel(const float* __restrict__ in, __half* __restrict__ out, int n8)
{
    int i = blockIdx.x * 256 + threadIdx.x;
    if (i >= n8) return;
    const float4* in4 = (const float4*)in;
    float4 a = in4[2 * i], b = in4[2 * i + 1];
    __half2* o = (__half2*)(out + 8LL * i);
    o[0] = __floats2half2_rn(a.x, a.y);
    o[1] = __floats2half2_rn(a.z, a.w);
    o[2] = __floats2half2_rn(b.x, b.y);
    o[3] = __floats2half2_rn(b.z, b.w);
}

// Transpose float [R][Cc] -> half [Cc][R]. R,Cc % 32 == 0.
__global__ void transpose_h_kernel(const float* __restrict__ in, __half* __restrict__ out,
                                   int R, int Cc)
{
    __shared__ float tile[32][33];
    int c0 = blockIdx.x * 32, r0 = blockIdx.y * 32;
    int tx = threadIdx.x, ty = threadIdx.y;
    #pragma unroll
    for (int i = 0; i < 32; i += 8)
        tile[ty + i][tx] = in[(long long)(r0 + ty + i) * Cc + c0 + tx];
    __syncthreads();
    #pragma unroll
    for (int i = 0; i < 32; i += 8)
        out[(long long)(c0 + ty + i) * R + r0 + tx] = __float2half(tile[tx][ty + i]);
}

// ---------------------------------------------------------------------------
// RoPE kernels
// ---------------------------------------------------------------------------
__global__ void rope_q_kernel(const float* __restrict__ in, __half* __restrict__ qcbuf,
                              const float* __restrict__ cosp, const float* __restrict__ sinp)
{
    int j = blockIdx.x * blockDim.x + threadIdx.x;
    if (j >= B_ * T_ * NH_ * (DHR_ / 2)) return;
    int i = j & 31;
    int h = (j >> 5) & 15;
    int t = (j >> 9) & 2047;
    int b = j >> 20;
    float c = cosp[t * 32 + i];
    float s = sinp[t * 32 + i];
    float re = in[2 * j], im = in[2 * j + 1];
    long long base = ((long long)(b * NH_ + h) * T_ + t) * KCAT + 512 + 2 * i;
    *(__half2*)(qcbuf + base) = __floats2half2_rn(re * c - im * s, re * s + im * c);
}

// Reads padded c_kr (half, [B*T][128], cols 0..63 valid), writes k_r into ckv cols 512:576.
__global__ void rope_k_kernel(const __half* __restrict__ in, __half* __restrict__ ckvbuf,
                              const float* __restrict__ cosp, const float* __restrict__ sinp)
{
    int j = blockIdx.x * blockDim.x + threadIdx.x;
    if (j >= B_ * T_ * (DHR_ / 2)) return;
    int i = j & 31;
    int t = (j >> 5) & 2047;
    int b = j >> 16;
    float c = cosp[t * 32 + i];
    float s = sinp[t * 32 + i];
    long long bt = (long long)b * T_ + t;
    __half2 v = *(const __half2*)(in + bt * 128 + 2 * i);
    float re = __half2float(v.x), im = __half2float(v.y);
    long long base = bt * KCAT + 512 + 2 * i;
    *(__half2*)(ckvbuf + base) = __floats2half2_rn(re * c - im * s, re * s + im * c);
}

// ---------------------------------------------------------------------------
// Causal softmax, fp16 in/out IN PLACE, fp32 math. One block per row.
// Writes cols [0, ceil128(t+1)) — exactly what the capped y GEMM reads.
// ---------------------------------------------------------------------------
__global__ void softmax_causal_kernel(__half* __restrict__ S)
{
    const float scale = 0.07216878364870323f;   // 1/sqrt(192)
    long long row = blockIdx.x;
    int t = (int)(row % T_);
    int limit = ((t >> 7) + 1) << 7;            // multiple of 128 covering t
    __half* p = S + row * (long long)T_;
    int tid = threadIdx.x;

    float v[8];
    float m = -3.0e38f;
    #pragma unroll
    for (int j = 0; j < 8; j++) {
        int i = tid + j * 256;
        float x = -3.0e38f;
        if (i <= t) x = __half2float(p[i]) * scale;
        v[j] = x;
        m = fmaxf(m, x);
    }

    __shared__ float red[256];
    red[tid] = m;
    __syncthreads();
    for (int s = 128; s > 0; s >>= 1) {
        if (tid < s) red[tid] = fmaxf(red[tid], red[tid + s]);
        __syncthreads();
    }
    m = red[0];
    __syncthreads();

    float sum = 0.f;
    #pragma unroll
    for (int j = 0; j < 8; j++) {
        int i = tid + j * 256;
        float e = (i <= t) ? __expf(v[j] - m) : 0.f;
        v[j] = e;
        sum += e;
    }
    red[tid] = sum;
    __syncthreads();
    for (int s = 128; s > 0; s >>= 1) {
        if (tid < s) red[tid] += red[tid + s];
        __syncthreads();
    }
    float inv = 1.0f / red[0];

    #pragma unroll
    for (int j = 0; j < 8; j++) {
        int i = tid + j * 256;
        if (i < limit) p[i] = __float2half(v[j] * inv);
    }
}

// ---------------------------------------------------------------------------
// Host
// ---------------------------------------------------------------------------
static inline void launch_h(const __half* A, const __half* B, void* C,
                            int M, int N, int K, int lda, int ldb, int ldc,
                            int batches, int HB,
                            long long sAb, long long sAh,
                            long long sBb, long long sBh,
                            long long sCb, long long sCh,
                            int outh, int causal)
{
    dim3 grid(N / 128, M / 128, batches);
    hgemm<<<grid, 256, SMEM_BYTES>>>(A, B, C, K, lda, ldb, ldc, HB,
                                     sAb, sAh, sBb, sBh, sCb, sCh, outh, causal);
}

static inline void f2h(const float* in, __half* out, long long n)
{
    int n8 = (int)(n / 8);
    f2h_kernel<<<(n8 + 255) / 256, 256>>>(in, out, n8);
}

static inline void transpose_h(const float* in, __half* out, int R, int Cc)
{
    dim3 grid(Cc / 32, R / 32);
    transpose_h_kernel<<<grid, dim3(32, 8)>>>(in, out, R, Cc);
}

extern "C" void kernel_launch(void* const* d_in, const int* in_sizes, int n_in,
                              void* d_out, int out_size)
{
    (void)in_sizes; (void)n_in; (void)out_size;
    const float* x     = (const float*)d_in[0];
    const float* cosp  = (const float*)d_in[1];
    const float* sinp  = (const float*)d_in[2];
    const float* W_dq  = (const float*)d_in[3];
    const float* W_uq  = (const float*)d_in[4];
    const float* W_dkv = (const float*)d_in[5];
    const float* W_uk  = (const float*)d_in[6];
    const float* W_uv  = (const float*)d_in[7];
    const float* W_qr  = (const float*)d_in[8];
    const float* W_kr  = (const float*)d_in[9];
    const float* W_o   = (const float*)d_in[10];
    float* y = (float*)d_out;

    static int smem_set = 0;
    if (!smem_set) {
        cudaFuncSetAttribute(hgemm, cudaFuncAttributeMaxDynamicSharedMemorySize, SMEM_BYTES);
        smem_set = 1;
    }

    __half *xh, *wdq, *wdkv, *wqr, *wo, *wuq, *wukT, *wuvT, *wkrp;
    __half *cq, *ckv, *keffT, *Rt, *qc, *VT, *S, *ckrp;
    float *cqr;
    cudaGetSymbolAddress((void**)&xh,    g_xh);
    cudaGetSymbolAddress((void**)&wdq,   g_wdq);
    cudaGetSymbolAddress((void**)&wdkv,  g_wdkv);
    cudaGetSymbolAddress((void**)&wqr,   g_wqr);
    cudaGetSymbolAddress((void**)&wo,    g_wo);
    cudaGetSymbolAddress((void**)&wuq,   g_wuq);
    cudaGetSymbolAddress((void**)&wukT,  g_wukT);
    cudaGetSymbolAddress((void**)&wuvT,  g_wuvT);
    cudaGetSymbolAddress((void**)&wkrp,  g_wkrp);
    cudaGetSymbolAddress((void**)&cq,    g_cq);
    cudaGetSymbolAddress((void**)&ckv,   g_ckv);
    cudaGetSymbolAddress((void**)&keffT, g_keffT);
    cudaGetSymbolAddress((void**)&Rt,    g_Rt);
    cudaGetSymbolAddress((void**)&qc,    g_qc);
    cudaGetSymbolAddress((void**)&VT,    g_VT);
    cudaGetSymbolAddress((void**)&S,     g_S);
    cudaGetSymbolAddress((void**)&ckrp,  g_ckrp);
    cudaGetSymbolAddress((void**)&cqr,   g_cqr);

    const long long TT   = (long long)T_ * T_;
    const long long T512 = (long long)T_ * 512;
    const long long TKC  = (long long)T_ * KCAT;
    const long long TC   = (long long)T_ * C_;

    // 0) fp16 conversions (5 launches), then the 6th launch is a GEMM so the
    //    ncu -s 5 -c 1 window lands near hgemm for the next analysis round.
    f2h(x,     xh,   (long long)B_*T_*C_);
    f2h(W_dq,  wdq,  (long long)NLQ_*C_);
    f2h(W_dkv, wdkv, (long long)NLKV_*C_);
    f2h(W_qr,  wqr,  (long long)NH_*DHR_*NLQ_);
    f2h(W_o,   wo,   (long long)C_*C_);

    // 1) c_q = xh @ wdq^T   [4096,512] (half out)
    launch_h(xh, wdq, cq, B_*T_, NLQ_, C_, C_, C_, NLQ_,
             1, 1, 0,0, 0,0, 0,0, 1, 0);

    // Remaining weight preps:
    // W_uq plain convert (reshape view), W_uk/W_uv transpose, W_kr into padded
    // [128][2048] buffer (rows 64..127 are never written -> stay zero-initialized).
    f2h(W_uq, wuq, (long long)C_*NLQ_);
    transpose_h(W_uk, wukT, C_, NLKV_);
    transpose_h(W_uv, wuvT, C_, NLKV_);
    f2h(W_kr, wkrp, (long long)DHR_*C_);

    // 2) c_kv = xh @ wdkv^T -> ckv buffer (half, ldc=576)
    launch_h(xh, wdkv, ckv, B_*T_, NLKV_, C_, C_, C_, KCAT,
             1, 1, 0,0, 0,0, 0,0, 1, 0);
    // 3) keffT[h][k][q] = sum_d wukT[k][h*128+d] * wuq[q][h*128+d]  (16 batched)
    launch_h(wukT, wuq, keffT, NLKV_, NLQ_, HS_, C_, C_, NLQ_,
             NH_, NH_, 0, HS_, 0, HS_, 0, (long long)NLKV_*NLQ_, 1, 0);
    // 4) Rt = wo @ wuvT^T   [2048,512] (half)
    launch_h(wo, wuvT, Rt, C_, NLKV_, C_, C_, C_, NLKV_,
             1, 1, 0,0, 0,0, 0,0, 1, 0);
    // 5) q_c[b,h] = cq[b] @ keffT[h]^T -> qc buffer (half, ldc=576)
    launch_h(cq, keffT, qc, T_, NLKV_, NLQ_, NLQ_, NLQ_, KCAT,
             B_*NH_, NH_, T512, 0, 0, (long long)NLKV_*NLQ_,
             (long long)NH_*TKC, TKC, 1, 0);
    // 6) c_qr = cq @ wqr^T  [4096,1024] (float out; rope converts)
    launch_h(cq, wqr, cqr, B_*T_, NH_*DHR_, NLQ_, NLQ_, NLQ_, NH_*DHR_,
             1, 1, 0,0, 0,0, 0,0, 0, 0);
    // 7) q_r = rope(c_qr) -> qc buffer cols [512:576] (half)
    {
        int n = B_ * T_ * NH_ * (DHR_ / 2);
        rope_q_kernel<<<(n + 255) / 256, 256>>>(cqr, qc, cosp, sinp);
    }
    // 8) c_kr (padded): ckrp = xh @ wkrp^T  [4096,128x2048] tensor-core (half out)
    launch_h(xh, wkrp, ckrp, B_*T_, 128, C_, C_, C_, 128,
             1, 1, 0,0, 0,0, 0,0, 1, 0);
    // 9) k_r = rope(ckrp cols 0:64) -> ckv buffer cols [512:576] (half)
    {
        int n = B_ * T_ * (DHR_ / 2);
        rope_k_kernel<<<(n + 255) / 256, 256>>>(ckrp, ckv, cosp, sinp);
    }
    // 10) S = [q_c|q_r] @ [c_kv|k_r]^T  (32 batched, 2048x2048x576, causal-skip, HALF out)
    launch_h(qc, ckv, S, T_, T_, KCAT, KCAT, KCAT, T_,
             B_*NH_, NH_, (long long)NH_*TKC, TKC, TKC, 0,
             (long long)NH_*TT, TT, 1, 2);
    // 11) VT[b][c][t] = sum_k Rt[c][k] * ckv[b][t][k]  (2 batched, half out)
    launch_h(Rt, ckv, VT, C_, T_, NLKV_, NLKV_, KCAT, T_,
             B_, 1, 0, 0, TKC, 0, TC, 0, 1, 0);
    // 12) causal softmax in place on half S, cols [0, ceil128(t+1))
    softmax_causal_kernel<<<B_*NH_*T_, 256>>>(S);
    // 13) y[b][t][h*128+c] = sum_s P[b,h][t][s] * VT[b][h*128+c][s]
    //     (32 batched, 2048x128x2048, K capped at row0+128, fp32 out)
    launch_h(S, VT, y, T_, HS_, T_, T_, T_, C_,
             B_*NH_, NH_, (long long)NH_*TT, TT, TC, (long long)HS_*T_,
             TC, HS_, 0, 1);
}

// round 15
// speedup vs baseline: 1.6061x; 1.0758x over previous
#include <cuda_runtime.h>
#include <cuda_fp16.h>

// Problem constants
#define B_    2
#define T_    2048
#define C_    2048
#define NH_   16
#define HS_   128
#define NLQ_  512
#define NLKV_ 512
#define DHR_  64

#define KCAT  576   // 512 + 64 concatenated K for fused S GEMM

// ---------------------------------------------------------------------------
// Static scratch (half operands for all tensor GEMMs; fp32 where needed)
// ---------------------------------------------------------------------------
__device__ __align__(256) __half g_xh  [B_*T_*C_];
__device__ __align__(256) __half g_wdq [NLQ_*C_];
__device__ __align__(256) __half g_wdkv[NLKV_*C_];
__device__ __align__(256) __half g_wqr [NH_*DHR_*NLQ_];
__device__ __align__(256) __half g_wo  [C_*C_];
__device__ __align__(256) __half g_wuq [NLQ_*C_];      // reshape view of W_uq
__device__ __align__(256) __half g_wukT[NLKV_*C_];     // transpose of W_uk
__device__ __align__(256) __half g_wuvT[NLKV_*C_];     // transpose of W_uv
__device__ __align__(256) __half g_wkrp[128*C_];       // W_kr padded 64->128 rows (pad stays 0)

__device__ __align__(256) __half g_cq   [B_*T_*NLQ_];
__device__ __align__(256) __half g_ckv  [B_*T_*KCAT];  // [0:512]=c_kv, [512:576]=k_r
__device__ __align__(256) __half g_keffT[NH_*NLKV_*NLQ_];
__device__ __align__(256) __half g_Rt   [C_*NLKV_];
__device__ __align__(256) __half g_qc   [B_*NH_*T_*KCAT]; // [0:512]=q_c, [512:576]=q_r
__device__ __align__(256) __half g_VT   [B_*C_*T_];    // VT[b] = Rt @ ckv[b]^T
__device__ __align__(256) __half g_S    [134217728];   // 256 MB scores->probs (half, in-place)
__device__ __align__(256) __half g_ckrp [B_*T_*128];   // c_kr padded

__device__ float g_cqr [B_*T_*NH_*DHR_];

// ---------------------------------------------------------------------------
__device__ __forceinline__ void mma_f16(float* c, const unsigned* a, const unsigned* b) {
    asm volatile(
        "mma.sync.aligned.m16n8k16.row.col.f32.f16.f16.f32 "
        "{%0,%1,%2,%3},{%4,%5,%6,%7},{%8,%9},{%0,%1,%2,%3};\n"
        : "+f"(c[0]), "+f"(c[1]), "+f"(c[2]), "+f"(c[3])
        : "r"(a[0]), "r"(a[1]), "r"(a[2]), "r"(a[3]), "r"(b[0]), "r"(b[1]));
}

__device__ __forceinline__ void ldsm4(unsigned* r, unsigned a) {
    asm volatile("ldmatrix.sync.aligned.m8n8.x4.shared.b16 {%0,%1,%2,%3}, [%4];"
                 : "=r"(r[0]), "=r"(r[1]), "=r"(r[2]), "=r"(r[3]) : "r"(a));
}

__device__ __forceinline__ void cp16(void* dst, const __half* src) {
    unsigned d = (unsigned)__cvta_generic_to_shared(dst);
    asm volatile("cp.async.cg.shared.global [%0], [%1], 16;\n" :: "r"(d), "l"(src));
}

// ---------------------------------------------------------------------------
// FP16 tensor-core batched GEMM: C[m,n] = sum_k A[m,k] * B[n,k]  (always B^T)
//   A,B half; C float (outh=0) or half (outh=1); fp32 accumulation.
//   CTA 128x128x32, 3-stage cp.async pipeline, 8 warps (4m x 2n),
//   warp tile 32x64; fragments via ldmatrix.x4 (12 LDSM per k-tile, was 48 LDS.32).
//   causal bit1: skip CTA if col0 > row0 ; bit0: cap K at row0+128.
// ---------------------------------------------------------------------------
#define STG_H 10240   // halfs per stage (As 128*40 + Bs 128*40)
#define SMEM_BYTES (3 * STG_H * 2)   // 61440

__global__ void __launch_bounds__(256, 2) hgemm(
    const __half* __restrict__ A, const __half* __restrict__ B, void* __restrict__ Cv,
    int K, int lda, int ldb, int ldc, int HB,
    long long sAb, long long sAh,
    long long sBb, long long sBh,
    long long sCb, long long sCh,
    int outh, int causal)
{
    if ((causal & 2) && (blockIdx.x > blockIdx.y)) return;

    extern __shared__ __half smh[];

    const int z  = blockIdx.z;
    const int bb = z / HB, hh = z - bb * HB;
    A += bb * sAb + hh * sAh;
    B += bb * sBb + hh * sBh;
    const long long coff = bb * sCb + hh * sCh;

    const int row0 = blockIdx.y * 128;
    const int col0 = blockIdx.x * 128;

    const int tid  = threadIdx.x;
    const int warp = tid >> 5, lane = tid & 31;
    const int wm = warp >> 1, wn = warp & 1;     // 4(m) x 2(n)
    const int g  = lane >> 2, t = lane & 3;

    // ldmatrix per-lane addressing (half-element offsets within a stage)
    const int a_row = wm * 32 + (lane & 7) + ((lane >> 3) & 1) * 8;
    const int a_col = ((lane >> 4) & 1) * 8;
    const int b_row = wn * 64 + (lane & 7) + ((lane >> 4) & 1) * 8;
    const int b_col = ((lane >> 3) & 1) * 8;

    const unsigned smh_s = (unsigned)__cvta_generic_to_shared(smh);

    float acc[2][8][4];
    #pragma unroll
    for (int i = 0; i < 2; i++)
        #pragma unroll
        for (int j = 0; j < 8; j++)
            #pragma unroll
            for (int q = 0; q < 4; q++) acc[i][j][q] = 0.f;

    int nk = K >> 5;
    if (causal & 1) {
        int cap = (row0 + 128) >> 5;
        if (cap < nk) nk = cap;
    }

    // As/Bs: [row 0..127][k 0..31] halfs, row stride 40
#define ISSUE(KT)                                                                         \
    do {                                                                                  \
        if ((KT) < nk) {                                                                  \
            const int k0_ = (KT) * 32;                                                    \
            __half* As_ = smh + ((KT) % 3) * STG_H;                                       \
            __half* Bs_ = As_ + 5120;                                                     \
            _Pragma("unroll")                                                             \
            for (int j = 0; j < 2; j++) {                                                 \
                int idx = tid + j * 256;                                                  \
                int row = idx >> 2, q = idx & 3;                                          \
                cp16(As_ + row * 40 + q * 8,                                              \
                     A + (long long)(row0 + row) * lda + k0_ + q * 8);                    \
                cp16(Bs_ + row * 40 + q * 8,                                              \
                     B + (long long)(col0 + row) * ldb + k0_ + q * 8);                    \
            }                                                                             \
        }                                                                                 \
        asm volatile("cp.async.commit_group;\n");                                        \
    } while (0)

    ISSUE(0);
    ISSUE(1);

    for (int kt = 0; kt < nk; kt++) {
        ISSUE(kt + 2);
        asm volatile("cp.async.wait_group 2;\n" ::: "memory");
        __syncthreads();

        const unsigned As_s = smh_s + ((kt % 3) * STG_H) * 2;
        const unsigned Bs_s = As_s + 5120 * 2;

        // A fragments for both kk halves up front (4 LDSM)
        unsigned af[2][2][4];   // [m-tile][kk/16][reg]
        #pragma unroll
        for (int i = 0; i < 2; i++)
            #pragma unroll
            for (int kq = 0; kq < 2; kq++)
                ldsm4(af[i][kq], As_s + (unsigned)(((a_row + i * 16) * 40 + a_col + kq * 16) * 2));

        #pragma unroll
        for (int kq = 0; kq < 2; kq++) {
            unsigned bf[8][2];
            #pragma unroll
            for (int jj = 0; jj < 8; jj += 2) {
                unsigned tmp[4];
                ldsm4(tmp, Bs_s + (unsigned)(((b_row + jj * 8) * 40 + b_col + kq * 16) * 2));
                bf[jj][0] = tmp[0]; bf[jj][1] = tmp[1];
                bf[jj + 1][0] = tmp[2]; bf[jj + 1][1] = tmp[3];
            }
            #pragma unroll
            for (int i = 0; i < 2; i++)
                #pragma unroll
                for (int j = 0; j < 8; j++)
                    mma_f16(acc[i][j], af[i][kq], bf[j]);
        }
        __syncthreads();
    }
#undef ISSUE

    // Epilogue
    if (outh) {
        __half* Ch = (__half*)Cv + coff;
        #pragma unroll
        for (int i = 0; i < 2; i++) {
            long long r0 = row0 + wm * 32 + i * 16 + g;
            #pragma unroll
            for (int j = 0; j < 8; j++) {
                int cc = col0 + wn * 64 + j * 8 + 2 * t;
                *(__half2*)(Ch + r0 * ldc + cc) =
                    __floats2half2_rn(acc[i][j][0], acc[i][j][1]);
                *(__half2*)(Ch + (r0 + 8) * ldc + cc) =
                    __floats2half2_rn(acc[i][j][2], acc[i][j][3]);
            }
        }
    } else {
        float* Cf = (float*)Cv + coff;
        #pragma unroll
        for (int i = 0; i < 2; i++) {
            long long r0 = row0 + wm * 32 + i * 16 + g;
            #pragma unroll
            for (int j = 0; j < 8; j++) {
                int cc = col0 + wn * 64 + j * 8 + 2 * t;
                *(float2*)(Cf + r0 * ldc + cc) =
                    make_float2(acc[i][j][0], acc[i][j][1]);
                *(float2*)(Cf + (r0 + 8) * ldc + cc) =
                    make_float2(acc[i][j][2], acc[i][j][3]);
            }
        }
    }
}

// ---------------------------------------------------------------------------
// float -> half conversion (n % 8 == 0)
// ---------------------------------------------------------------------------
__global__ void f2h_kernel(const float* __restrict__ in, __half* __restrict__ out, int n8)
{
    int i = blockIdx.x * 256 + threadIdx.x;
    if (i >= n8) return;
    const float4* in4 = (const float4*)in;
    float4 a = in4[2 * i], b = in4[2 * i + 1];
    __half2* o = (__half2*)(out + 8LL * i);
    o[0] = __floats2half2_rn(a.x, a.y);
    o[1] = __floats2half2_rn(a.z, a.w);
    o[2] = __floats2half2_rn(b.x, b.y);
    o[3] = __floats2half2_rn(b.z, b.w);
}

// Transpose float [R][Cc] -> half [Cc][R]. R,Cc % 32 == 0.
__global__ void transpose_h_kernel(const float* __restrict__ in, __half* __restrict__ out,
                                   int R, int Cc)
{
    __shared__ float tile[32][33];
    int c0 = blockIdx.x * 32, r0 = blockIdx.y * 32;
    int tx = threadIdx.x, ty = threadIdx.y;
    #pragma unroll
    for (int i = 0; i < 32; i += 8)
        tile[ty + i][tx] = in[(long long)(r0 + ty + i) * Cc + c0 + tx];
    __syncthreads();
    #pragma unroll
    for (int i = 0; i < 32; i += 8)
        out[(long long)(c0 + ty + i) * R + r0 + tx] = __float2half(tile[tx][ty + i]);
}

// ---------------------------------------------------------------------------
// RoPE kernels
// ---------------------------------------------------------------------------
__global__ void rope_q_kernel(const float* __restrict__ in, __half* __restrict__ qcbuf,
                              const float* __restrict__ cosp, const float* __restrict__ sinp)
{
    int j = blockIdx.x * blockDim.x + threadIdx.x;
    if (j >= B_ * T_ * NH_ * (DHR_ / 2)) return;
    int i = j & 31;
    int h = (j >> 5) & 15;
    int t = (j >> 9) & 2047;
    int b = j >> 20;
    float c = cosp[t * 32 + i];
    float s = sinp[t * 32 + i];
    float re = in[2 * j], im = in[2 * j + 1];
    long long base = ((long long)(b * NH_ + h) * T_ + t) * KCAT + 512 + 2 * i;
    *(__half2*)(qcbuf + base) = __floats2half2_rn(re * c - im * s, re * s + im * c);
}

// Reads padded c_kr (half, [B*T][128], cols 0..63 valid), writes k_r into ckv cols 512:576.
__global__ void rope_k_kernel(const __half* __restrict__ in, __half* __restrict__ ckvbuf,
                              const float* __restrict__ cosp, const float* __restrict__ sinp)
{
    int j = blockIdx.x * blockDim.x + threadIdx.x;
    if (j >= B_ * T_ * (DHR_ / 2)) return;
    int i = j & 31;
    int t = (j >> 5) & 2047;
    int b = j >> 16;
    float c = cosp[t * 32 + i];
    float s = sinp[t * 32 + i];
    long long bt = (long long)b * T_ + t;
    __half2 v = *(const __half2*)(in + bt * 128 + 2 * i);
    float re = __half2float(v.x), im = __half2float(v.y);
    long long base = bt * KCAT + 512 + 2 * i;
    *(__half2*)(ckvbuf + base) = __floats2half2_rn(re * c - im * s, re * s + im * c);
}

// ---------------------------------------------------------------------------
// Causal softmax, fp16 in/out IN PLACE, fp32 math. One block per row.
// Writes cols [0, ceil128(t+1)) — exactly what the capped y GEMM reads.
// ---------------------------------------------------------------------------
__global__ void softmax_causal_kernel(__half* __restrict__ S)
{
    const float scale = 0.07216878364870323f;   // 1/sqrt(192)
    long long row = blockIdx.x;
    int t = (int)(row % T_);
    int limit = ((t >> 7) + 1) << 7;            // multiple of 128 covering t
    __half* p = S + row * (long long)T_;
    int tid = threadIdx.x;

    float v[8];
    float m = -3.0e38f;
    #pragma unroll
    for (int j = 0; j < 8; j++) {
        int i = tid + j * 256;
        float x = -3.0e38f;
        if (i <= t) x = __half2float(p[i]) * scale;
        v[j] = x;
        m = fmaxf(m, x);
    }

    __shared__ float red[256];
    red[tid] = m;
    __syncthreads();
    for (int s = 128; s > 0; s >>= 1) {
        if (tid < s) red[tid] = fmaxf(red[tid], red[tid + s]);
        __syncthreads();
    }
    m = red[0];
    __syncthreads();

    float sum = 0.f;
    #pragma unroll
    for (int j = 0; j < 8; j++) {
        int i = tid + j * 256;
        float e = (i <= t) ? __expf(v[j] - m) : 0.f;
        v[j] = e;
        sum += e;
    }
    red[tid] = sum;
    __syncthreads();
    for (int s = 128; s > 0; s >>= 1) {
        if (tid < s) red[tid] += red[tid + s];
        __syncthreads();
    }
    float inv = 1.0f / red[0];

    #pragma unroll
    for (int j = 0; j < 8; j++) {
        int i = tid + j * 256;
        if (i < limit) p[i] = __float2half(v[j] * inv);
    }
}

// ---------------------------------------------------------------------------
// Host
// ---------------------------------------------------------------------------
static inline void launch_h(const __half* A, const __half* B, void* C,
                            int M, int N, int K, int lda, int ldb, int ldc,
                            int batches, int HB,
                            long long sAb, long long sAh,
                            long long sBb, long long sBh,
                            long long sCb, long long sCh,
                            int outh, int causal)
{
    dim3 grid(N / 128, M / 128, batches);
    hgemm<<<grid, 256, SMEM_BYTES>>>(A, B, C, K, lda, ldb, ldc, HB,
                                     sAb, sAh, sBb, sBh, sCb, sCh, outh, causal);
}

static inline void f2h(const float* in, __half* out, long long n)
{
    int n8 = (int)(n / 8);
    f2h_kernel<<<(n8 + 255) / 256, 256>>>(in, out, n8);
}

static inline void transpose_h(const float* in, __half* out, int R, int Cc)
{
    dim3 grid(Cc / 32, R / 32);
    transpose_h_kernel<<<grid, dim3(32, 8)>>>(in, out, R, Cc);
}

extern "C" void kernel_launch(void* const* d_in, const int* in_sizes, int n_in,
                              void* d_out, int out_size)
{
    (void)in_sizes; (void)n_in; (void)out_size;
    const float* x     = (const float*)d_in[0];
    const float* cosp  = (const float*)d_in[1];
    const float* sinp  = (const float*)d_in[2];
    const float* W_dq  = (const float*)d_in[3];
    const float* W_uq  = (const float*)d_in[4];
    const float* W_dkv = (const float*)d_in[5];
    const float* W_uk  = (const float*)d_in[6];
    const float* W_uv  = (const float*)d_in[7];
    const float* W_qr  = (const float*)d_in[8];
    const float* W_kr  = (const float*)d_in[9];
    const float* W_o   = (const float*)d_in[10];
    float* y = (float*)d_out;

    static int smem_set = 0;
    if (!smem_set) {
        cudaFuncSetAttribute(hgemm, cudaFuncAttributeMaxDynamicSharedMemorySize, SMEM_BYTES);
        smem_set = 1;
    }

    __half *xh, *wdq, *wdkv, *wqr, *wo, *wuq, *wukT, *wuvT, *wkrp;
    __half *cq, *ckv, *keffT, *Rt, *qc, *VT, *S, *ckrp;
    float *cqr;
    cudaGetSymbolAddress((void**)&xh,    g_xh);
    cudaGetSymbolAddress((void**)&wdq,   g_wdq);
    cudaGetSymbolAddress((void**)&wdkv,  g_wdkv);
    cudaGetSymbolAddress((void**)&wqr,   g_wqr);
    cudaGetSymbolAddress((void**)&wo,    g_wo);
    cudaGetSymbolAddress((void**)&wuq,   g_wuq);
    cudaGetSymbolAddress((void**)&wukT,  g_wukT);
    cudaGetSymbolAddress((void**)&wuvT,  g_wuvT);
    cudaGetSymbolAddress((void**)&wkrp,  g_wkrp);
    cudaGetSymbolAddress((void**)&cq,    g_cq);
    cudaGetSymbolAddress((void**)&ckv,   g_ckv);
    cudaGetSymbolAddress((void**)&keffT, g_keffT);
    cudaGetSymbolAddress((void**)&Rt,    g_Rt);
    cudaGetSymbolAddress((void**)&qc,    g_qc);
    cudaGetSymbolAddress((void**)&VT,    g_VT);
    cudaGetSymbolAddress((void**)&S,     g_S);
    cudaGetSymbolAddress((void**)&ckrp,  g_ckrp);
    cudaGetSymbolAddress((void**)&cqr,   g_cqr);

    const long long TT   = (long long)T_ * T_;
    const long long T512 = (long long)T_ * 512;
    const long long TKC  = (long long)T_ * KCAT;
    const long long TC   = (long long)T_ * C_;

    // 0) fp16 conversions
    f2h(x,     xh,   (long long)B_*T_*C_);
    f2h(W_dq,  wdq,  (long long)NLQ_*C_);
    f2h(W_dkv, wdkv, (long long)NLKV_*C_);
    f2h(W_qr,  wqr,  (long long)NH_*DHR_*NLQ_);
    f2h(W_o,   wo,   (long long)C_*C_);

    // 1) c_q = xh @ wdq^T   [4096,512] (half out)
    launch_h(xh, wdq, cq, B_*T_, NLQ_, C_, C_, C_, NLQ_,
             1, 1, 0,0, 0,0, 0,0, 1, 0);

    // Remaining weight preps
    f2h(W_uq, wuq, (long long)C_*NLQ_);
    transpose_h(W_uk, wukT, C_, NLKV_);
    transpose_h(W_uv, wuvT, C_, NLKV_);
    f2h(W_kr, wkrp, (long long)DHR_*C_);

    // 2) c_kv = xh @ wdkv^T -> ckv buffer (half, ldc=576)
    launch_h(xh, wdkv, ckv, B_*T_, NLKV_, C_, C_, C_, KCAT,
             1, 1, 0,0, 0,0, 0,0, 1, 0);
    // 3) keffT[h][k][q] = sum_d wukT[k][h*128+d] * wuq[q][h*128+d]  (16 batched)
    launch_h(wukT, wuq, keffT, NLKV_, NLQ_, HS_, C_, C_, NLQ_,
             NH_, NH_, 0, HS_, 0, HS_, 0, (long long)NLKV_*NLQ_, 1, 0);
    // 4) Rt = wo @ wuvT^T   [2048,512] (half)
    launch_h(wo, wuvT, Rt, C_, NLKV_, C_, C_, C_, NLKV_,
             1, 1, 0,0, 0,0, 0,0, 1, 0);
    // 5) q_c[b,h] = cq[b] @ keffT[h]^T -> qc buffer (half, ldc=576)
    launch_h(cq, keffT, qc, T_, NLKV_, NLQ_, NLQ_, NLQ_, KCAT,
             B_*NH_, NH_, T512, 0, 0, (long long)NLKV_*NLQ_,
             (long long)NH_*TKC, TKC, 1, 0);
    // 6) c_qr = cq @ wqr^T  [4096,1024] (float out; rope converts)
    launch_h(cq, wqr, cqr, B_*T_, NH_*DHR_, NLQ_, NLQ_, NLQ_, NH_*DHR_,
             1, 1, 0,0, 0,0, 0,0, 0, 0);
    // 7) q_r = rope(c_qr) -> qc buffer cols [512:576] (half)
    {
        int n = B_ * T_ * NH_ * (DHR_ / 2);
        rope_q_kernel<<<(n + 255) / 256, 256>>>(cqr, qc, cosp, sinp);
    }
    // 8) c_kr (padded): ckrp = xh @ wkrp^T  [4096,128x2048] (half out)
    launch_h(xh, wkrp, ckrp, B_*T_, 128, C_, C_, C_, 128,
             1, 1, 0,0, 0,0, 0,0, 1, 0);
    // 9) k_r = rope(ckrp cols 0:64) -> ckv buffer cols [512:576] (half)
    {
        int n = B_ * T_ * (DHR_ / 2);
        rope_k_kernel<<<(n + 255) / 256, 256>>>(ckrp, ckv, cosp, sinp);
    }
    // 10) S = [q_c|q_r] @ [c_kv|k_r]^T  (32 batched, 2048x2048x576, causal-skip, half out)
    launch_h(qc, ckv, S, T_, T_, KCAT, KCAT, KCAT, T_,
             B_*NH_, NH_, (long long)NH_*TKC, TKC, TKC, 0,
             (long long)NH_*TT, TT, 1, 2);
    // 11) VT[b][c][t] = sum_k Rt[c][k] * ckv[b][t][k]  (2 batched, half out)
    launch_h(Rt, ckv, VT, C_, T_, NLKV_, NLKV_, KCAT, T_,
             B_, 1, 0, 0, TKC, 0, TC, 0, 1, 0);
    // 12) causal softmax in place on half S, cols [0, ceil128(t+1))
    softmax_causal_kernel<<<B_*NH_*T_, 256>>>(S);
    // 13) y[b][t][h*128+c] = sum_s P[b,h][t][s] * VT[b][h*128+c][s]
    //     (32 batched, 2048x128x2048, K capped at row0+128, fp32 out)
    launch_h(S, VT, y, T_, HS_, T_, T_, T_, C_,
             B_*NH_, NH_, (long long)NH_*TT, TT, TC, (long long)HS_*T_,
             TC, HS_, 0, 1);
}

// round 16
// speedup vs baseline: 2.0835x; 1.2973x over previous
#include <cuda_runtime.h>
#include <cuda_fp16.h>

// Problem constants
#define B_    2
#define T_    2048
#define C_    2048
#define NH_   16
#define HS_   128
#define NLQ_  512
#define NLKV_ 512
#define DHR_  64

#define KQH   192   // 128 (head dim) + 64 (rope) concatenated K for S GEMM

// ---------------------------------------------------------------------------
// Static scratch
// ---------------------------------------------------------------------------
__device__ __align__(256) __half g_xh  [B_*T_*C_];
__device__ __align__(256) __half g_wdq [NLQ_*C_];
__device__ __align__(256) __half g_wdkv[NLKV_*C_];
__device__ __align__(256) __half g_wqr [NH_*DHR_*NLQ_];
__device__ __align__(256) __half g_wo  [C_*C_];
__device__ __align__(256) __half g_wuqT[C_*NLQ_];      // transpose of W_uq reshape view
__device__ __align__(256) __half g_wuk [C_*NLKV_];     // W_uk as-is [C][NLKV]
__device__ __align__(256) __half g_wuvT[NLKV_*C_];     // transpose of W_uv
__device__ __align__(256) __half g_wkrp[128*C_];       // W_kr padded 64->128 rows (pad stays 0)

__device__ __align__(256) __half g_cq  [B_*T_*NLQ_];
__device__ __align__(256) __half g_ckv [B_*T_*NLKV_];
__device__ __align__(256) __half g_qh  [B_*NH_*T_*KQH]; // [0:128]=qh, [128:192]=q_r
__device__ __align__(256) __half g_kh  [B_*NH_*T_*KQH]; // [0:128]=kh, [128:192]=k_r
__device__ __align__(256) __half g_Rt  [C_*NLKV_];
__device__ __align__(256) __half g_VT  [B_*C_*T_];     // VT[b] = Rt @ ckv[b]^T
__device__ __align__(256) __half g_S   [134217728];    // 256 MB scores->probs (half, in-place)
__device__ __align__(256) __half g_ckrp[B_*T_*128];    // c_kr padded

__device__ float g_cqr [B_*T_*NH_*DHR_];

// ---------------------------------------------------------------------------
__device__ __forceinline__ void mma_f16(float* c, const unsigned* a, const unsigned* b) {
    asm volatile(
        "mma.sync.aligned.m16n8k16.row.col.f32.f16.f16.f32 "
        "{%0,%1,%2,%3},{%4,%5,%6,%7},{%8,%9},{%0,%1,%2,%3};\n"
        : "+f"(c[0]), "+f"(c[1]), "+f"(c[2]), "+f"(c[3])
        : "r"(a[0]), "r"(a[1]), "r"(a[2]), "r"(a[3]), "r"(b[0]), "r"(b[1]));
}

__device__ __forceinline__ void ldsm4(unsigned* r, unsigned a) {
    asm volatile("ldmatrix.sync.aligned.m8n8.x4.shared.b16 {%0,%1,%2,%3}, [%4];"
                 : "=r"(r[0]), "=r"(r[1]), "=r"(r[2]), "=r"(r[3]) : "r"(a));
}

__device__ __forceinline__ void cp16(void* dst, const __half* src) {
    unsigned d = (unsigned)__cvta_generic_to_shared(dst);
    asm volatile("cp.async.cg.shared.global [%0], [%1], 16;\n" :: "r"(d), "l"(src));
}

// ---------------------------------------------------------------------------
// FP16 tensor-core batched GEMM: C[m,n] = sum_k A[m,k] * B[n,k]  (always B^T)
//   A,B half; C float (outh=0) or half (outh=1); fp32 accumulation.
//   CTA 128x128x32, 3-stage cp.async pipeline, 8 warps (4m x 2n),
//   warp tile 32x64; fragments via ldmatrix.x4.
//   causal bit1: skip CTA if col0 > row0 ; bit0: cap K at row0+128.
// ---------------------------------------------------------------------------
#define STG_H 10240   // halfs per stage (As 128*40 + Bs 128*40)
#define SMEM_BYTES (3 * STG_H * 2)   // 61440

__global__ void __launch_bounds__(256, 2) hgemm(
    const __half* __restrict__ A, const __half* __restrict__ B, void* __restrict__ Cv,
    int K, int lda, int ldb, int ldc, int HB,
    long long sAb, long long sAh,
    long long sBb, long long sBh,
    long long sCb, long long sCh,
    int outh, int causal)
{
    if ((causal & 2) && (blockIdx.x > blockIdx.y)) return;

    extern __shared__ __half smh[];

    const int z  = blockIdx.z;
    const int bb = z / HB, hh = z - bb * HB;
    A += bb * sAb + hh * sAh;
    B += bb * sBb + hh * sBh;
    const long long coff = bb * sCb + hh * sCh;

    const int row0 = blockIdx.y * 128;
    const int col0 = blockIdx.x * 128;

    const int tid  = threadIdx.x;
    const int warp = tid >> 5, lane = tid & 31;
    const int wm = warp >> 1, wn = warp & 1;     // 4(m) x 2(n)
    const int g  = lane >> 2, t = lane & 3;

    // ldmatrix per-lane addressing (half-element offsets within a stage)
    const int a_row = wm * 32 + (lane & 7) + ((lane >> 3) & 1) * 8;
    const int a_col = ((lane >> 4) & 1) * 8;
    const int b_row = wn * 64 + (lane & 7) + ((lane >> 4) & 1) * 8;
    const int b_col = ((lane >> 3) & 1) * 8;

    const unsigned smh_s = (unsigned)__cvta_generic_to_shared(smh);

    float acc[2][8][4];
    #pragma unroll
    for (int i = 0; i < 2; i++)
        #pragma unroll
        for (int j = 0; j < 8; j++)
            #pragma unroll
            for (int q = 0; q < 4; q++) acc[i][j][q] = 0.f;

    int nk = K >> 5;
    if (causal & 1) {
        int cap = (row0 + 128) >> 5;
        if (cap < nk) nk = cap;
    }

    // As/Bs: [row 0..127][k 0..31] halfs, row stride 40
#define ISSUE(KT)                                                                         \
    do {                                                                                  \
        if ((KT) < nk) {                                                                  \
            const int k0_ = (KT) * 32;                                                    \
            __half* As_ = smh + ((KT) % 3) * STG_H;                                       \
            __half* Bs_ = As_ + 5120;                                                     \
            _Pragma("unroll")                                                             \
            for (int j = 0; j < 2; j++) {                                                 \
                int idx = tid + j * 256;                                                  \
                int row = idx >> 2, q = idx & 3;                                          \
                cp16(As_ + row * 40 + q * 8,                                              \
                     A + (long long)(row0 + row) * lda + k0_ + q * 8);                    \
                cp16(Bs_ + row * 40 + q * 8,                                              \
                     B + (long long)(col0 + row) * ldb + k0_ + q * 8);                    \
            }                                                                             \
        }                                                                                 \
        asm volatile("cp.async.commit_group;\n");                                        \
    } while (0)

    ISSUE(0);
    ISSUE(1);

    for (int kt = 0; kt < nk; kt++) {
        ISSUE(kt + 2);
        asm volatile("cp.async.wait_group 2;\n" ::: "memory");
        __syncthreads();

        const unsigned As_s = smh_s + ((kt % 3) * STG_H) * 2;
        const unsigned Bs_s = As_s + 5120 * 2;

        unsigned af[2][2][4];   // [m-tile][kk/16][reg]
        #pragma unroll
        for (int i = 0; i < 2; i++)
            #pragma unroll
            for (int kq = 0; kq < 2; kq++)
                ldsm4(af[i][kq], As_s + (unsigned)(((a_row + i * 16) * 40 + a_col + kq * 16) * 2));

        #pragma unroll
        for (int kq = 0; kq < 2; kq++) {
            unsigned bf[8][2];
            #pragma unroll
            for (int jj = 0; jj < 8; jj += 2) {
                unsigned tmp[4];
                ldsm4(tmp, Bs_s + (unsigned)(((b_row + jj * 8) * 40 + b_col + kq * 16) * 2));
                bf[jj][0] = tmp[0]; bf[jj][1] = tmp[1];
                bf[jj + 1][0] = tmp[2]; bf[jj + 1][1] = tmp[3];
            }
            #pragma unroll
            for (int i = 0; i < 2; i++)
                #pragma unroll
                for (int j = 0; j < 8; j++)
                    mma_f16(acc[i][j], af[i][kq], bf[j]);
        }
        __syncthreads();
    }
#undef ISSUE

    // Epilogue
    if (outh) {
        __half* Ch = (__half*)Cv + coff;
        #pragma unroll
        for (int i = 0; i < 2; i++) {
            long long r0 = row0 + wm * 32 + i * 16 + g;
            #pragma unroll
            for (int j = 0; j < 8; j++) {
                int cc = col0 + wn * 64 + j * 8 + 2 * t;
                *(__half2*)(Ch + r0 * ldc + cc) =
                    __floats2half2_rn(acc[i][j][0], acc[i][j][1]);
                *(__half2*)(Ch + (r0 + 8) * ldc + cc) =
                    __floats2half2_rn(acc[i][j][2], acc[i][j][3]);
            }
        }
    } else {
        float* Cf = (float*)Cv + coff;
        #pragma unroll
        for (int i = 0; i < 2; i++) {
            long long r0 = row0 + wm * 32 + i * 16 + g;
            #pragma unroll
            for (int j = 0; j < 8; j++) {
                int cc = col0 + wn * 64 + j * 8 + 2 * t;
                *(float2*)(Cf + r0 * ldc + cc) =
                    make_float2(acc[i][j][0], acc[i][j][1]);
                *(float2*)(Cf + (r0 + 8) * ldc + cc) =
                    make_float2(acc[i][j][2], acc[i][j][3]);
            }
        }
    }
}

// ---------------------------------------------------------------------------
// float -> half conversion (n % 8 == 0)
// ---------------------------------------------------------------------------
__global__ void f2h_kernel(const float* __restrict__ in, __half* __restrict__ out, int n8)
{
    int i = blockIdx.x * 256 + threadIdx.x;
    if (i >= n8) return;
    const float4* in4 = (const float4*)in;
    float4 a = in4[2 * i], b = in4[2 * i + 1];
    __half2* o = (__half2*)(out + 8LL * i);
    o[0] = __floats2half2_rn(a.x, a.y);
    o[1] = __floats2half2_rn(a.z, a.w);
    o[2] = __floats2half2_rn(b.x, b.y);
    o[3] = __floats2half2_rn(b.z, b.w);
}

// Transpose float [R][Cc] -> half [Cc][R]. R,Cc % 32 == 0.
__global__ void transpose_h_kernel(const float* __restrict__ in, __half* __restrict__ out,
                                   int R, int Cc)
{
    __shared__ float tile[32][33];
    int c0 = blockIdx.x * 32, r0 = blockIdx.y * 32;
    int tx = threadIdx.x, ty = threadIdx.y;
    #pragma unroll
    for (int i = 0; i < 32; i += 8)
        tile[ty + i][tx] = in[(long long)(r0 + ty + i) * Cc + c0 + tx];
    __syncthreads();
    #pragma unroll
    for (int i = 0; i < 32; i += 8)
        out[(long long)(c0 + ty + i) * R + r0 + tx] = __float2half(tile[tx][ty + i]);
}

// ---------------------------------------------------------------------------
// RoPE kernels
// ---------------------------------------------------------------------------
// q_r: float c_qr [B,T,NH,DHR] -> qh buffer cols [128:192], row stride KQH
__global__ void rope_q_kernel(const float* __restrict__ in, __half* __restrict__ qhbuf,
                              const float* __restrict__ cosp, const float* __restrict__ sinp)
{
    int j = blockIdx.x * blockDim.x + threadIdx.x;
    if (j >= B_ * T_ * NH_ * (DHR_ / 2)) return;
    int i = j & 31;
    int h = (j >> 5) & 15;
    int t = (j >> 9) & 2047;
    int b = j >> 20;
    float c = cosp[t * 32 + i];
    float s = sinp[t * 32 + i];
    float re = in[2 * j], im = in[2 * j + 1];
    long long base = ((long long)(b * NH_ + h) * T_ + t) * KQH + 128 + 2 * i;
    *(__half2*)(qhbuf + base) = __floats2half2_rn(re * c - im * s, re * s + im * c);
}

// k_r: padded c_kr (half, [B*T][128], cols 0..63 valid) -> kh buffer cols [128:192],
// replicated across all 16 heads.
__global__ void rope_k_kernel(const __half* __restrict__ in, __half* __restrict__ khbuf,
                              const float* __restrict__ cosp, const float* __restrict__ sinp)
{
    int j = blockIdx.x * blockDim.x + threadIdx.x;
    if (j >= B_ * T_ * (DHR_ / 2)) return;
    int i = j & 31;
    int t = (j >> 5) & 2047;
    int b = j >> 16;
    float c = cosp[t * 32 + i];
    float s = sinp[t * 32 + i];
    long long bt = (long long)b * T_ + t;
    __half2 v = *(const __half2*)(in + bt * 128 + 2 * i);
    float re = __half2float(v.x), im = __half2float(v.y);
    __half2 r = __floats2half2_rn(re * c - im * s, re * s + im * c);
    long long base = ((long long)b * NH_ * T_ + t) * 1;  // recompute per head below
    #pragma unroll
    for (int h = 0; h < NH_; h++) {
        long long off = ((long long)(b * NH_ + h) * T_ + t) * KQH + 128 + 2 * i;
        *(__half2*)(khbuf + off) = r;
    }
    (void)base;
}

// ---------------------------------------------------------------------------
// Causal softmax, fp16 in/out IN PLACE, fp32 math. One block per row.
// Writes cols [0, ceil128(t+1)) — exactly what the capped y GEMM reads.
// ---------------------------------------------------------------------------
__global__ void softmax_causal_kernel(__half* __restrict__ S)
{
    const float scale = 0.07216878364870323f;   // 1/sqrt(192)
    long long row = blockIdx.x;
    int t = (int)(row % T_);
    int limit = ((t >> 7) + 1) << 7;            // multiple of 128 covering t
    __half* p = S + row * (long long)T_;
    int tid = threadIdx.x;

    float v[8];
    float m = -3.0e38f;
    #pragma unroll
    for (int j = 0; j < 8; j++) {
        int i = tid + j * 256;
        float x = -3.0e38f;
        if (i <= t) x = __half2float(p[i]) * scale;
        v[j] = x;
        m = fmaxf(m, x);
    }

    __shared__ float red[256];
    red[tid] = m;
    __syncthreads();
    for (int s = 128; s > 0; s >>= 1) {
        if (tid < s) red[tid] = fmaxf(red[tid], red[tid + s]);
        __syncthreads();
    }
    m = red[0];
    __syncthreads();

    float sum = 0.f;
    #pragma unroll
    for (int j = 0; j < 8; j++) {
        int i = tid + j * 256;
        float e = (i <= t) ? __expf(v[j] - m) : 0.f;
        v[j] = e;
        sum += e;
    }
    red[tid] = sum;
    __syncthreads();
    for (int s = 128; s > 0; s >>= 1) {
        if (tid < s) red[tid] += red[tid + s];
        __syncthreads();
    }
    float inv = 1.0f / red[0];

    #pragma unroll
    for (int j = 0; j < 8; j++) {
        int i = tid + j * 256;
        if (i < limit) p[i] = __float2half(v[j] * inv);
    }
}

// ---------------------------------------------------------------------------
// Host
// ---------------------------------------------------------------------------
static inline void launch_h(const __half* A, const __half* B, void* C,
                            int M, int N, int K, int lda, int ldb, int ldc,
                            int batches, int HB,
                            long long sAb, long long sAh,
                            long long sBb, long long sBh,
                            long long sCb, long long sCh,
                            int outh, int causal)
{
    dim3 grid(N / 128, M / 128, batches);
    hgemm<<<grid, 256, SMEM_BYTES>>>(A, B, C, K, lda, ldb, ldc, HB,
                                     sAb, sAh, sBb, sBh, sCb, sCh, outh, causal);
}

static inline void f2h(const float* in, __half* out, long long n)
{
    int n8 = (int)(n / 8);
    f2h_kernel<<<(n8 + 255) / 256, 256>>>(in, out, n8);
}

static inline void transpose_h(const float* in, __half* out, int R, int Cc)
{
    dim3 grid(Cc / 32, R / 32);
    transpose_h_kernel<<<grid, dim3(32, 8)>>>(in, out, R, Cc);
}

extern "C" void kernel_launch(void* const* d_in, const int* in_sizes, int n_in,
                              void* d_out, int out_size)
{
    (void)in_sizes; (void)n_in; (void)out_size;
    const float* x     = (const float*)d_in[0];
    const float* cosp  = (const float*)d_in[1];
    const float* sinp  = (const float*)d_in[2];
    const float* W_dq  = (const float*)d_in[3];
    const float* W_uq  = (const float*)d_in[4];
    const float* W_dkv = (const float*)d_in[5];
    const float* W_uk  = (const float*)d_in[6];
    const float* W_uv  = (const float*)d_in[7];
    const float* W_qr  = (const float*)d_in[8];
    const float* W_kr  = (const float*)d_in[9];
    const float* W_o   = (const float*)d_in[10];
    float* y = (float*)d_out;

    static int smem_set = 0;
    if (!smem_set) {
        cudaFuncSetAttribute(hgemm, cudaFuncAttributeMaxDynamicSharedMemorySize, SMEM_BYTES);
        smem_set = 1;
    }

    __half *xh, *wdq, *wdkv, *wqr, *wo, *wuqT, *wuk, *wuvT, *wkrp;
    __half *cq, *ckv, *qh, *kh, *Rt, *VT, *S, *ckrp;
    float *cqr;
    cudaGetSymbolAddress((void**)&xh,   g_xh);
    cudaGetSymbolAddress((void**)&wdq,  g_wdq);
    cudaGetSymbolAddress((void**)&wdkv, g_wdkv);
    cudaGetSymbolAddress((void**)&wqr,  g_wqr);
    cudaGetSymbolAddress((void**)&wo,   g_wo);
    cudaGetSymbolAddress((void**)&wuqT, g_wuqT);
    cudaGetSymbolAddress((void**)&wuk,  g_wuk);
    cudaGetSymbolAddress((void**)&wuvT, g_wuvT);
    cudaGetSymbolAddress((void**)&wkrp, g_wkrp);
    cudaGetSymbolAddress((void**)&cq,   g_cq);
    cudaGetSymbolAddress((void**)&ckv,  g_ckv);
    cudaGetSymbolAddress((void**)&qh,   g_qh);
    cudaGetSymbolAddress((void**)&kh,   g_kh);
    cudaGetSymbolAddress((void**)&Rt,   g_Rt);
    cudaGetSymbolAddress((void**)&VT,   g_VT);
    cudaGetSymbolAddress((void**)&S,    g_S);
    cudaGetSymbolAddress((void**)&ckrp, g_ckrp);
    cudaGetSymbolAddress((void**)&cqr,  g_cqr);

    const long long TT   = (long long)T_ * T_;
    const long long T512 = (long long)T_ * 512;
    const long long TKQ  = (long long)T_ * KQH;
    const long long TC   = (long long)T_ * C_;

    // 0) fp16 conversions (5 launches, then GEMM is 6th for the ncu window)
    f2h(x,     xh,   (long long)B_*T_*C_);
    f2h(W_dq,  wdq,  (long long)NLQ_*C_);
    f2h(W_dkv, wdkv, (long long)NLKV_*C_);
    f2h(W_qr,  wqr,  (long long)NH_*DHR_*NLQ_);
    f2h(W_o,   wo,   (long long)C_*C_);

    // 1) c_q = xh @ wdq^T   [4096,512] (half out)
    launch_h(xh, wdq, cq, B_*T_, NLQ_, C_, C_, C_, NLQ_,
             1, 1, 0,0, 0,0, 0,0, 1, 0);

    // Remaining weight preps:
    //  wuqT[c][q] = W_uq reshape view transposed  ([NLQ][C] -> [C][NLQ])
    //  wuk  = W_uk as-is [C][NLKV] (half)
    //  wuvT = W_uv transposed ([C][NLKV] -> [NLKV][C])
    //  wkrp = W_kr padded 64->128 rows
    transpose_h(W_uq, wuqT, NLQ_, C_);
    f2h(W_uk, wuk, (long long)C_*NLKV_);
    transpose_h(W_uv, wuvT, C_, NLKV_);
    f2h(W_kr, wkrp, (long long)DHR_*C_);

    // 2) c_kv = xh @ wdkv^T  [4096,512] (half, ldc=512)
    launch_h(xh, wdkv, ckv, B_*T_, NLKV_, C_, C_, C_, NLKV_,
             1, 1, 0,0, 0,0, 0,0, 1, 0);
    // 3) qh[b,h][t][d] = sum_q cq[b][t][q] * wuqT[h*128+d][q]
    //    (32 batched, 2048x128x512 -> qh buffer cols 0:128, ldc=192)
    launch_h(cq, wuqT, qh, T_, HS_, NLQ_, NLQ_, NLQ_, KQH,
             B_*NH_, NH_, T512, 0, 0, (long long)HS_*NLQ_,
             (long long)NH_*TKQ, TKQ, 1, 0);
    // 4) kh[b,h][s][d] = sum_k ckv[b][s][k] * W_uk[h*128+d][k]
    //    (32 batched, 2048x128x512 -> kh buffer cols 0:128, ldc=192)
    launch_h(ckv, wuk, kh, T_, HS_, NLKV_, NLKV_, NLKV_, KQH,
             B_*NH_, NH_, T512, 0, 0, (long long)HS_*NLKV_,
             (long long)NH_*TKQ, TKQ, 1, 0);
    // 5) Rt = wo @ wuvT^T   [2048,512] (half)
    launch_h(wo, wuvT, Rt, C_, NLKV_, C_, C_, C_, NLKV_,
             1, 1, 0,0, 0,0, 0,0, 1, 0);
    // 6) c_qr = cq @ wqr^T  [4096,1024] (float out; rope converts)
    launch_h(cq, wqr, cqr, B_*T_, NH_*DHR_, NLQ_, NLQ_, NLQ_, NH_*DHR_,
             1, 1, 0,0, 0,0, 0,0, 0, 0);
    // 7) q_r = rope(c_qr) -> qh buffer cols [128:192]
    {
        int n = B_ * T_ * NH_ * (DHR_ / 2);
        rope_q_kernel<<<(n + 255) / 256, 256>>>(cqr, qh, cosp, sinp);
    }
    // 8) c_kr (padded): ckrp = xh @ wkrp^T  [4096,128x2048] (half out)
    launch_h(xh, wkrp, ckrp, B_*T_, 128, C_, C_, C_, 128,
             1, 1, 0,0, 0,0, 0,0, 1, 0);
    // 9) k_r = rope(ckrp) -> kh buffer cols [128:192], replicated over heads
    {
        int n = B_ * T_ * (DHR_ / 2);
        rope_k_kernel<<<(n + 255) / 256, 256>>>(ckrp, kh, cosp, sinp);
    }
    // 10) S = qh @ kh^T  (32 batched, 2048x2048x192, causal-skip, half out)
    launch_h(qh, kh, S, T_, T_, KQH, KQH, KQH, T_,
             B_*NH_, NH_, (long long)NH_*TKQ, TKQ, (long long)NH_*TKQ, TKQ,
             (long long)NH_*TT, TT, 1, 2);
    // 11) VT[b][c][t] = sum_k Rt[c][k] * ckv[b][t][k]  (2 batched, half out)
    launch_h(Rt, ckv, VT, C_, T_, NLKV_, NLKV_, NLKV_, T_,
             B_, 1, 0, 0, T512, 0, TC, 0, 1, 0);
    // 12) causal softmax in place on half S, cols [0, ceil128(t+1))
    softmax_causal_kernel<<<B_*NH_*T_, 256>>>(S);
    // 13) y[b][t][h*128+c] = sum_s P[b,h][t][s] * VT[b][h*128+c][s]
    //     (32 batched, 2048x128x2048, K capped at row0+128, fp32 out)
    launch_h(S, VT, y, T_, HS_, T_, T_, T_, C_,
             B_*NH_, NH_, (long long)NH_*TT, TT, TC, (long long)HS_*T_,
             TC, HS_, 0, 1);
}

// round 17
// speedup vs baseline: 2.3515x; 1.1286x over previous
#include <cuda_runtime.h>
#include <cuda_fp16.h>

// Problem constants
#define B_    2
#define T_    2048
#define C_    2048
#define NH_   16
#define HS_   128
#define NLQ_  512
#define NLKV_ 512
#define DHR_  64

#define KQH   192   // 128 (head dim) + 64 (rope) concatenated K for S GEMM
#define NCAT  1152  // 512 (c_q) + 512 (c_kv) + 64 (c_kr) + 64 pad

// ---------------------------------------------------------------------------
// Static scratch
// ---------------------------------------------------------------------------
__device__ __align__(256) __half g_xh  [B_*T_*C_];
__device__ __align__(256) __half g_wcat[NCAT*C_];      // [0:512]=W_dq, [512:1024]=W_dkv, [1024:1088]=W_kr, rest 0
__device__ __align__(256) __half g_wqr [NH_*DHR_*NLQ_];
__device__ __align__(256) __half g_wo  [C_*C_];
__device__ __align__(256) __half g_wuqT[C_*NLQ_];      // transpose of W_uq reshape view
__device__ __align__(256) __half g_wuk [C_*NLKV_];     // W_uk as-is [C][NLKV]
__device__ __align__(256) __half g_wuvT[NLKV_*C_];     // transpose of W_uv

__device__ __align__(256) __half g_cqkv[B_*T_*NCAT];   // [0:512]=c_q, [512:1024]=c_kv, [1024:1088]=c_kr
__device__ __align__(256) __half g_qh  [B_*NH_*T_*KQH]; // [0:128]=qh, [128:192]=q_r
__device__ __align__(256) __half g_kh  [B_*NH_*T_*KQH]; // [0:128]=kh, [128:192]=k_r
__device__ __align__(256) __half g_Rt  [C_*NLKV_];
__device__ __align__(256) __half g_VT  [B_*C_*T_];     // VT[b] = Rt @ ckv[b]^T
__device__ __align__(256) __half g_S   [134217728];    // 256 MB scores->probs (half, in-place)

__device__ float g_cqr [B_*T_*NH_*DHR_];

// ---------------------------------------------------------------------------
__device__ __forceinline__ void mma_f16(float* c, const unsigned* a, const unsigned* b) {
    asm volatile(
        "mma.sync.aligned.m16n8k16.row.col.f32.f16.f16.f32 "
        "{%0,%1,%2,%3},{%4,%5,%6,%7},{%8,%9},{%0,%1,%2,%3};\n"
        : "+f"(c[0]), "+f"(c[1]), "+f"(c[2]), "+f"(c[3])
        : "r"(a[0]), "r"(a[1]), "r"(a[2]), "r"(a[3]), "r"(b[0]), "r"(b[1]));
}

__device__ __forceinline__ void ldsm4(unsigned* r, unsigned a) {
    asm volatile("ldmatrix.sync.aligned.m8n8.x4.shared.b16 {%0,%1,%2,%3}, [%4];"
                 : "=r"(r[0]), "=r"(r[1]), "=r"(r[2]), "=r"(r[3]) : "r"(a));
}

__device__ __forceinline__ void cp16(void* dst, const __half* src) {
    unsigned d = (unsigned)__cvta_generic_to_shared(dst);
    asm volatile("cp.async.cg.shared.global [%0], [%1], 16;\n" :: "r"(d), "l"(src));
}

// ---------------------------------------------------------------------------
// FP16 tensor-core batched GEMM: C[m,n] = sum_k A[m,k] * B[n,k]  (always B^T)
//   A,B half; C float (outh=0) or half (outh=1); fp32 accumulation.
//   CTA 128x128x32, 3-stage cp.async pipeline, 8 warps (4m x 2n),
//   warp tile 32x64; fragments via ldmatrix.x4.
//   causal bit1: skip CTA if col0 > row0 ; bit0: cap K at row0+128.
// ---------------------------------------------------------------------------
#define STG_H 10240   // halfs per stage (As 128*40 + Bs 128*40)
#define SMEM_BYTES (3 * STG_H * 2)   // 61440

__global__ void __launch_bounds__(256, 2) hgemm(
    const __half* __restrict__ A, const __half* __restrict__ B, void* __restrict__ Cv,
    int K, int lda, int ldb, int ldc, int HB,
    long long sAb, long long sAh,
    long long sBb, long long sBh,
    long long sCb, long long sCh,
    int outh, int causal)
{
    if ((causal & 2) && (blockIdx.x > blockIdx.y)) return;

    extern __shared__ __half smh[];

    const int z  = blockIdx.z;
    const int bb = z / HB, hh = z - bb * HB;
    A += bb * sAb + hh * sAh;
    B += bb * sBb + hh * sBh;
    const long long coff = bb * sCb + hh * sCh;

    const int row0 = blockIdx.y * 128;
    const int col0 = blockIdx.x * 128;

    const int tid  = threadIdx.x;
    const int warp = tid >> 5, lane = tid & 31;
    const int wm = warp >> 1, wn = warp & 1;     // 4(m) x 2(n)
    const int g  = lane >> 2, t = lane & 3;

    const int a_row = wm * 32 + (lane & 7) + ((lane >> 3) & 1) * 8;
    const int a_col = ((lane >> 4) & 1) * 8;
    const int b_row = wn * 64 + (lane & 7) + ((lane >> 4) & 1) * 8;
    const int b_col = ((lane >> 3) & 1) * 8;

    const unsigned smh_s = (unsigned)__cvta_generic_to_shared(smh);

    float acc[2][8][4];
    #pragma unroll
    for (int i = 0; i < 2; i++)
        #pragma unroll
        for (int j = 0; j < 8; j++)
            #pragma unroll
            for (int q = 0; q < 4; q++) acc[i][j][q] = 0.f;

    int nk = K >> 5;
    if (causal & 1) {
        int cap = (row0 + 128) >> 5;
        if (cap < nk) nk = cap;
    }

    // As/Bs: [row 0..127][k 0..31] halfs, row stride 40
#define ISSUE(KT)                                                                         \
    do {                                                                                  \
        if ((KT) < nk) {                                                                  \
            const int k0_ = (KT) * 32;                                                    \
            __half* As_ = smh + ((KT) % 3) * STG_H;                                       \
            __half* Bs_ = As_ + 5120;                                                     \
            _Pragma("unroll")                                                             \
            for (int j = 0; j < 2; j++) {                                                 \
                int idx = tid + j * 256;                                                  \
                int row = idx >> 2, q = idx & 3;                                          \
                cp16(As_ + row * 40 + q * 8,                                              \
                     A + (long long)(row0 + row) * lda + k0_ + q * 8);                    \
                cp16(Bs_ + row * 40 + q * 8,                                              \
                     B + (long long)(col0 + row) * ldb + k0_ + q * 8);                    \
            }                                                                             \
        }                                                                                 \
        asm volatile("cp.async.commit_group;\n");                                        \
    } while (0)

    ISSUE(0);
    ISSUE(1);

    for (int kt = 0; kt < nk; kt++) {
        ISSUE(kt + 2);
        asm volatile("cp.async.wait_group 2;\n" ::: "memory");
        __syncthreads();

        const unsigned As_s = smh_s + ((kt % 3) * STG_H) * 2;
        const unsigned Bs_s = As_s + 5120 * 2;

        unsigned af[2][2][4];   // [m-tile][kk/16][reg]
        #pragma unroll
        for (int i = 0; i < 2; i++)
            #pragma unroll
            for (int kq = 0; kq < 2; kq++)
                ldsm4(af[i][kq], As_s + (unsigned)(((a_row + i * 16) * 40 + a_col + kq * 16) * 2));

        #pragma unroll
        for (int kq = 0; kq < 2; kq++) {
            unsigned bf[8][2];
            #pragma unroll
            for (int jj = 0; jj < 8; jj += 2) {
                unsigned tmp[4];
                ldsm4(tmp, Bs_s + (unsigned)(((b_row + jj * 8) * 40 + b_col + kq * 16) * 2));
                bf[jj][0] = tmp[0]; bf[jj][1] = tmp[1];
                bf[jj + 1][0] = tmp[2]; bf[jj + 1][1] = tmp[3];
            }
            #pragma unroll
            for (int i = 0; i < 2; i++)
                #pragma unroll
                for (int j = 0; j < 8; j++)
                    mma_f16(acc[i][j], af[i][kq], bf[j]);
        }
        __syncthreads();
    }
#undef ISSUE

    // Epilogue
    if (outh) {
        __half* Ch = (__half*)Cv + coff;
        #pragma unroll
        for (int i = 0; i < 2; i++) {
            long long r0 = row0 + wm * 32 + i * 16 + g;
            #pragma unroll
            for (int j = 0; j < 8; j++) {
                int cc = col0 + wn * 64 + j * 8 + 2 * t;
                *(__half2*)(Ch + r0 * ldc + cc) =
                    __floats2half2_rn(acc[i][j][0], acc[i][j][1]);
                *(__half2*)(Ch + (r0 + 8) * ldc + cc) =
                    __floats2half2_rn(acc[i][j][2], acc[i][j][3]);
            }
        }
    } else {
        float* Cf = (float*)Cv + coff;
        #pragma unroll
        for (int i = 0; i < 2; i++) {
            long long r0 = row0 + wm * 32 + i * 16 + g;
            #pragma unroll
            for (int j = 0; j < 8; j++) {
                int cc = col0 + wn * 64 + j * 8 + 2 * t;
                *(float2*)(Cf + r0 * ldc + cc) =
                    make_float2(acc[i][j][0], acc[i][j][1]);
                *(float2*)(Cf + (r0 + 8) * ldc + cc) =
                    make_float2(acc[i][j][2], acc[i][j][3]);
            }
        }
    }
}

// ---------------------------------------------------------------------------
// float -> half conversion (n % 8 == 0)
// ---------------------------------------------------------------------------
__global__ void f2h_kernel(const float* __restrict__ in, __half* __restrict__ out, int n8)
{
    int i = blockIdx.x * 256 + threadIdx.x;
    if (i >= n8) return;
    const float4* in4 = (const float4*)in;
    float4 a = in4[2 * i], b = in4[2 * i + 1];
    __half2* o = (__half2*)(out + 8LL * i);
    o[0] = __floats2half2_rn(a.x, a.y);
    o[1] = __floats2half2_rn(a.z, a.w);
    o[2] = __floats2half2_rn(b.x, b.y);
    o[3] = __floats2half2_rn(b.z, b.w);
}

// Transpose float [R][Cc] -> half [Cc][R]. R,Cc % 32 == 0.
__global__ void transpose_h_kernel(const float* __restrict__ in, __half* __restrict__ out,
                                   int R, int Cc)
{
    __shared__ float tile[32][33];
    int c0 = blockIdx.x * 32, r0 = blockIdx.y * 32;
    int tx = threadIdx.x, ty = threadIdx.y;
    #pragma unroll
    for (int i = 0; i < 32; i += 8)
        tile[ty + i][tx] = in[(long long)(r0 + ty + i) * Cc + c0 + tx];
    __syncthreads();
    #pragma unroll
    for (int i = 0; i < 32; i += 8)
        out[(long long)(c0 + ty + i) * R + r0 + tx] = __float2half(tile[tx][ty + i]);
}

// ---------------------------------------------------------------------------
// RoPE kernels
// ---------------------------------------------------------------------------
// q_r: float c_qr [B,T,NH,DHR] -> qh buffer cols [128:192], row stride KQH
__global__ void rope_q_kernel(const float* __restrict__ in, __half* __restrict__ qhbuf,
                              const float* __restrict__ cosp, const float* __restrict__ sinp)
{
    int j = blockIdx.x * blockDim.x + threadIdx.x;
    if (j >= B_ * T_ * NH_ * (DHR_ / 2)) return;
    int i = j & 31;
    int h = (j >> 5) & 15;
    int t = (j >> 9) & 2047;
    int b = j >> 20;
    float c = cosp[t * 32 + i];
    float s = sinp[t * 32 + i];
    float re = in[2 * j], im = in[2 * j + 1];
    long long base = ((long long)(b * NH_ + h) * T_ + t) * KQH + 128 + 2 * i;
    *(__half2*)(qhbuf + base) = __floats2half2_rn(re * c - im * s, re * s + im * c);
}

// k_r: c_kr lives in cqkv cols [1024:1088] -> kh buffer cols [128:192], replicated over heads
__global__ void rope_k_kernel(const __half* __restrict__ cqkv, __half* __restrict__ khbuf,
                              const float* __restrict__ cosp, const float* __restrict__ sinp)
{
    int j = blockIdx.x * blockDim.x + threadIdx.x;
    if (j >= B_ * T_ * (DHR_ / 2)) return;
    int i = j & 31;
    int t = (j >> 5) & 2047;
    int b = j >> 16;
    float c = cosp[t * 32 + i];
    float s = sinp[t * 32 + i];
    long long bt = (long long)b * T_ + t;
    __half2 v = *(const __half2*)(cqkv + bt * NCAT + 1024 + 2 * i);
    float re = __half2float(v.x), im = __half2float(v.y);
    __half2 r = __floats2half2_rn(re * c - im * s, re * s + im * c);
    #pragma unroll
    for (int h = 0; h < NH_; h++) {
        long long off = ((long long)(b * NH_ + h) * T_ + t) * KQH + 128 + 2 * i;
        *(__half2*)(khbuf + off) = r;
    }
}

// ---------------------------------------------------------------------------
// Causal softmax, fp16 in/out IN PLACE, fp32 math, base-2 exponent.
// One block (256 threads) per row; dynamic iteration count; shuffle reductions.
// Writes cols [0, ceil128(t+1)) — exactly what the capped y GEMM reads.
// ---------------------------------------------------------------------------
__global__ void softmax_causal_kernel(__half* __restrict__ S)
{
    // scale2 = (1/sqrt(192)) * log2(e): exp(x*scale) == exp2(x*scale2)
    const float scale2 = 0.10412625204909879f;
    long long row = blockIdx.x;
    int t = (int)(row & (T_ - 1));
    int limit = ((t >> 7) + 1) << 7;            // multiple of 128 covering t
    __half2* p2 = (__half2*)(S + row * (long long)T_);
    int tid = threadIdx.x;
    const int nj = (limit + 511) >> 9;          // 1..4 iterations of 512 cols

    float2 v[4];
    float m = -3.0e38f;
    #pragma unroll 4
    for (int j = 0; j < nj; j++) {
        int i2 = tid + j * 256;
        int i = 2 * i2;
        float2 x = make_float2(-3.0e38f, -3.0e38f);
        if (i < limit) {
            __half2 h = p2[i2];
            float lo = __low2float(h), hi = __high2float(h);
            if (i     <= t) x.x = lo * scale2;
            if (i + 1 <= t) x.y = hi * scale2;
        }
        v[j] = x;
        m = fmaxf(m, fmaxf(x.x, x.y));
    }

    __shared__ float red[8];
    #pragma unroll
    for (int o = 16; o > 0; o >>= 1) m = fmaxf(m, __shfl_xor_sync(0xFFFFFFFFu, m, o));
    if ((tid & 31) == 0) red[tid >> 5] = m;
    __syncthreads();
    m = red[0];
    #pragma unroll
    for (int w = 1; w < 8; w++) m = fmaxf(m, red[w]);
    __syncthreads();                            // protect red[] reuse

    float sum = 0.f;
    #pragma unroll 4
    for (int j = 0; j < nj; j++) {
        float ex = exp2f(v[j].x - m);           // masked: -3e38 - m -> exp2 -> 0
        float ey = exp2f(v[j].y - m);
        v[j].x = ex; v[j].y = ey;
        sum += ex + ey;
    }
    #pragma unroll
    for (int o = 16; o > 0; o >>= 1) sum += __shfl_xor_sync(0xFFFFFFFFu, sum, o);
    if ((tid & 31) == 0) red[tid >> 5] = sum;
    __syncthreads();
    sum = red[0];
    #pragma unroll
    for (int w = 1; w < 8; w++) sum += red[w];
    float inv = 1.0f / sum;

    #pragma unroll 4
    for (int j = 0; j < nj; j++) {
        int i2 = tid + j * 256;
        if (2 * i2 < limit)
            p2[i2] = __floats2half2_rn(v[j].x * inv, v[j].y * inv);
    }
}

// ---------------------------------------------------------------------------
// Host
// ---------------------------------------------------------------------------
static inline void launch_h(const __half* A, const __half* B, void* C,
                            int M, int N, int K, int lda, int ldb, int ldc,
                            int batches, int HB,
                            long long sAb, long long sAh,
                            long long sBb, long long sBh,
                            long long sCb, long long sCh,
                            int outh, int causal)
{
    dim3 grid(N / 128, M / 128, batches);
    hgemm<<<grid, 256, SMEM_BYTES>>>(A, B, C, K, lda, ldb, ldc, HB,
                                     sAb, sAh, sBb, sBh, sCb, sCh, outh, causal);
}

static inline void f2h(const float* in, __half* out, long long n)
{
    int n8 = (int)(n / 8);
    f2h_kernel<<<(n8 + 255) / 256, 256>>>(in, out, n8);
}

static inline void transpose_h(const float* in, __half* out, int R, int Cc)
{
    dim3 grid(Cc / 32, R / 32);
    transpose_h_kernel<<<grid, dim3(32, 8)>>>(in, out, R, Cc);
}

extern "C" void kernel_launch(void* const* d_in, const int* in_sizes, int n_in,
                              void* d_out, int out_size)
{
    (void)in_sizes; (void)n_in; (void)out_size;
    const float* x     = (const float*)d_in[0];
    const float* cosp  = (const float*)d_in[1];
    const float* sinp  = (const float*)d_in[2];
    const float* W_dq  = (const float*)d_in[3];
    const float* W_uq  = (const float*)d_in[4];
    const float* W_dkv = (const float*)d_in[5];
    const float* W_uk  = (const float*)d_in[6];
    const float* W_uv  = (const float*)d_in[7];
    const float* W_qr  = (const float*)d_in[8];
    const float* W_kr  = (const float*)d_in[9];
    const float* W_o   = (const float*)d_in[10];
    float* y = (float*)d_out;

    static int smem_set = 0;
    if (!smem_set) {
        cudaFuncSetAttribute(hgemm, cudaFuncAttributeMaxDynamicSharedMemorySize, SMEM_BYTES);
        smem_set = 1;
    }

    __half *xh, *wcat, *wqr, *wo, *wuqT, *wuk, *wuvT;
    __half *cqkv, *qh, *kh, *Rt, *VT, *S;
    float *cqr;
    cudaGetSymbolAddress((void**)&xh,   g_xh);
    cudaGetSymbolAddress((void**)&wcat, g_wcat);
    cudaGetSymbolAddress((void**)&wqr,  g_wqr);
    cudaGetSymbolAddress((void**)&wo,   g_wo);
    cudaGetSymbolAddress((void**)&wuqT, g_wuqT);
    cudaGetSymbolAddress((void**)&wuk,  g_wuk);
    cudaGetSymbolAddress((void**)&wuvT, g_wuvT);
    cudaGetSymbolAddress((void**)&cqkv, g_cqkv);
    cudaGetSymbolAddress((void**)&qh,   g_qh);
    cudaGetSymbolAddress((void**)&kh,   g_kh);
    cudaGetSymbolAddress((void**)&Rt,   g_Rt);
    cudaGetSymbolAddress((void**)&VT,   g_VT);
    cudaGetSymbolAddress((void**)&S,    g_S);
    cudaGetSymbolAddress((void**)&cqr,  g_cqr);

    const long long TT   = (long long)T_ * T_;
    const long long TNC  = (long long)T_ * NCAT;
    const long long TKQ  = (long long)T_ * KQH;
    const long long TC   = (long long)T_ * C_;

    // 0) fp16 conversions / weight prep
    f2h(x,     xh,   (long long)B_*T_*C_);
    f2h(W_dq,  wcat,                 (long long)NLQ_*C_);    // rows 0:512
    f2h(W_dkv, wcat + 512LL*C_,      (long long)NLKV_*C_);   // rows 512:1024
    f2h(W_kr,  wcat + 1024LL*C_,     (long long)DHR_*C_);    // rows 1024:1088 (1088:1152 stay 0)
    f2h(W_qr,  wqr,  (long long)NH_*DHR_*NLQ_);
    f2h(W_o,   wo,   (long long)C_*C_);
    transpose_h(W_uq, wuqT, NLQ_, C_);   // [NLQ][C] -> [C][NLQ]
    f2h(W_uk, wuk, (long long)C_*NLKV_);
    transpose_h(W_uv, wuvT, C_, NLKV_);  // [C][NLKV] -> [NLKV][C]

    // 1) Fused projection: cqkv = xh @ wcat^T  [4096 x 1152 x 2048] (half out)
    //    cols 0:512 = c_q, 512:1024 = c_kv, 1024:1088 = c_kr
    launch_h(xh, wcat, cqkv, B_*T_, NCAT, C_, C_, C_, NCAT,
             1, 1, 0,0, 0,0, 0,0, 1, 0);
    // 2) qh[b,h][t][d] = sum_q c_q[b][t][q] * wuqT[h*128+d][q]
    //    (32 batched, 2048x128x512 -> qh cols 0:128, ldc=192)
    launch_h(cqkv, wuqT, qh, T_, HS_, NLQ_, NCAT, NLQ_, KQH,
             B_*NH_, NH_, TNC, 0, 0, (long long)HS_*NLQ_,
             (long long)NH_*TKQ, TKQ, 1, 0);
    // 3) kh[b,h][s][d] = sum_k c_kv[b][s][k] * W_uk[h*128+d][k]
    launch_h(cqkv + 512, wuk, kh, T_, HS_, NLKV_, NCAT, NLKV_, KQH,
             B_*NH_, NH_, TNC, 0, 0, (long long)HS_*NLKV_,
             (long long)NH_*TKQ, TKQ, 1, 0);
    // 4) Rt = wo @ wuvT^T   [2048,512] (half)
    launch_h(wo, wuvT, Rt, C_, NLKV_, C_, C_, C_, NLKV_,
             1, 1, 0,0, 0,0, 0,0, 1, 0);
    // 5) c_qr = c_q @ wqr^T  [4096,1024] (float out; rope converts)
    launch_h(cqkv, wqr, cqr, B_*T_, NH_*DHR_, NLQ_, NCAT, NLQ_, NH_*DHR_,
             1, 1, 0,0, 0,0, 0,0, 0, 0);
    // 6) q_r = rope(c_qr) -> qh cols [128:192]
    {
        int n = B_ * T_ * NH_ * (DHR_ / 2);
        rope_q_kernel<<<(n + 255) / 256, 256>>>(cqr, qh, cosp, sinp);
    }
    // 7) k_r = rope(c_kr in cqkv) -> kh cols [128:192], replicated over heads
    {
        int n = B_ * T_ * (DHR_ / 2);
        rope_k_kernel<<<(n + 255) / 256, 256>>>(cqkv, kh, cosp, sinp);
    }
    // 8) S = qh @ kh^T  (32 batched, 2048x2048x192, causal-skip, half out)
    launch_h(qh, kh, S, T_, T_, KQH, KQH, KQH, T_,
             B_*NH_, NH_, (long long)NH_*TKQ, TKQ, (long long)NH_*TKQ, TKQ,
             (long long)NH_*TT, TT, 1, 2);
    // 9) VT[b][c][t] = sum_k Rt[c][k] * c_kv[b][t][k]  (2 batched, half out)
    launch_h(Rt, cqkv + 512, VT, C_, T_, NLKV_, NLKV_, NCAT, T_,
             B_, 1, 0, 0, TNC, 0, TC, 0, 1, 0);
    // 10) causal softmax in place on half S, cols [0, ceil128(t+1))
    softmax_causal_kernel<<<B_*NH_*T_, 256>>>(S);
    // 11) y[b][t][h*128+c] = sum_s P[b,h][t][s] * VT[b][h*128+c][s]
    //     (32 batched, 2048x128x2048, K capped at row0+128, fp32 out)
    launch_h(S, VT, y, T_, HS_, T_, T_, T_, C_,
             B_*NH_, NH_, (long long)NH_*TT, TT, TC, (long long)HS_*T_,
             TC, HS_, 0, 1);
}